// round 2
// baseline (speedup 1.0000x reference)
#include <cuda_runtime.h>
#include <math.h>

// ---------------- problem constants ----------------
#define BATCH 32
#define NPROP 256
#define NCLS  19
#define NPTS  4096
#define NBQ   64
#define NCK   64
#define CDIM  256
#define QHD   768
#define VQ    8
#define NOUT  (VQ*QHD)                 // 6144
#define MROWS (BATCH*NBQ)              // 2048 rows per branch
#define FEAT_PER_B ((NBQ+NCK)*VQ*QHD)  // 786432
#define FEAT_TOTAL ((size_t)BATCH*FEAT_PER_B)
#define BOX_HALF   (NBQ*VQ*QHD)        // 393216

// ---------------- scratch (no allocs allowed) ----------------
__device__ float g_mnp[BATCH*NPROP*3];
__device__ float g_mxp[BATCH*NPROP*3];
__device__ float g_volp[BATCH*NPROP];
__device__ float g_maskp[BATCH*NPROP];
__device__ float g_mnq[BATCH*NBQ*3];
__device__ float g_mxq[BATCH*NBQ*3];
__device__ float g_volq[BATCH*NBQ];
__device__ float g_Xbox[MROWS*CDIM];
__device__ float g_Xclick[MROWS*2*CDIM];
__device__ float g_Hbox[MROWS*QHD];
__device__ float g_Hclick[MROWS*QHD];

// ---------------- kernel 1: proposal sem-mask + AABB ----------------
__global__ void prep_props_kernel(const float* __restrict__ logits,
                                  const float* __restrict__ corners) {
    int i = blockIdx.x * blockDim.x + threadIdx.x;
    if (i >= BATCH*NPROP) return;
    // argmax over 19 classes (first-max tie break)
    const float* lg = logits + (size_t)i*NCLS;
    int am = 0; float best = lg[0];
    #pragma unroll
    for (int c = 1; c < NCLS; c++) { float v = lg[c]; if (v > best) { best = v; am = c; } }
    g_maskp[i] = (am != NCLS-1) ? 1.0f : 0.0f;
    // min/max over 8 corners
    const float* cr = corners + (size_t)i*24;
    float mn[3] = {cr[0], cr[1], cr[2]};
    float mx[3] = {cr[0], cr[1], cr[2]};
    #pragma unroll
    for (int k = 1; k < 8; k++) {
        #pragma unroll
        for (int d = 0; d < 3; d++) {
            float v = cr[k*3+d];
            mn[d] = fminf(mn[d], v);
            mx[d] = fmaxf(mx[d], v);
        }
    }
    float vol = 1.0f;
    #pragma unroll
    for (int d = 0; d < 3; d++) {
        g_mnp[i*3+d] = mn[d]; g_mxp[i*3+d] = mx[d];
        vol *= (mx[d] - mn[d]);
    }
    g_volp[i] = vol;
}

// ---------------- kernel 2: query AABB ----------------
__global__ void prep_queries_kernel(const float* __restrict__ box_query) {
    int i = blockIdx.x * blockDim.x + threadIdx.x;
    if (i >= BATCH*NBQ) return;
    const float* cr = box_query + (size_t)i*24;
    float mn[3] = {cr[0], cr[1], cr[2]};
    float mx[3] = {cr[0], cr[1], cr[2]};
    #pragma unroll
    for (int k = 1; k < 8; k++)
        #pragma unroll
        for (int d = 0; d < 3; d++) {
            float v = cr[k*3+d];
            mn[d] = fminf(mn[d], v);
            mx[d] = fmaxf(mx[d], v);
        }
    float vol = 1.0f;
    #pragma unroll
    for (int d = 0; d < 3; d++) {
        g_mnq[i*3+d] = mn[d]; g_mxq[i*3+d] = mx[d];
        vol *= (mx[d] - mn[d]);
    }
    g_volq[i] = vol;
}

// ---------------- kernel 3: IoU argmax match + gather ----------------
__global__ __launch_bounds__(256) void box_match_kernel(const float* __restrict__ prop_features) {
    int m = blockIdx.x;          // b*NBQ + q
    int b = m >> 6;
    int tid = threadIdx.x;       // one proposal per thread
    float mnq0 = g_mnq[m*3+0], mnq1 = g_mnq[m*3+1], mnq2 = g_mnq[m*3+2];
    float mxq0 = g_mxq[m*3+0], mxq1 = g_mxq[m*3+1], mxq2 = g_mxq[m*3+2];
    float volq = g_volq[m];
    int pi = b*NPROP + tid;
    float i0 = fmaxf(fminf(mxq0, g_mxp[pi*3+0]) - fmaxf(mnq0, g_mnp[pi*3+0]), 0.0f);
    float i1 = fmaxf(fminf(mxq1, g_mxp[pi*3+1]) - fmaxf(mnq1, g_mnp[pi*3+1]), 0.0f);
    float i2 = fmaxf(fminf(mxq2, g_mxp[pi*3+2]) - fmaxf(mnq2, g_mnp[pi*3+2]), 0.0f);
    float inter = i0*i1*i2;
    float iou = inter / (volq + g_volp[pi] - inter + 1e-8f);
    iou *= g_maskp[pi];

    __shared__ float sv[256];
    __shared__ int   si[256];
    sv[tid] = iou; si[tid] = tid;
    __syncthreads();
    #pragma unroll
    for (int off = 128; off > 0; off >>= 1) {
        if (tid < off) {
            float v2 = sv[tid+off]; int j2 = si[tid+off];
            if (v2 > sv[tid] || (v2 == sv[tid] && j2 < si[tid])) { sv[tid] = v2; si[tid] = j2; }
        }
        __syncthreads();
    }
    int idx = si[0];
    // gather proposal feature row -> Xbox
    g_Xbox[(size_t)m*CDIM + tid] = prop_features[((size_t)b*NPROP + idx)*CDIM + tid];
}

// ---------------- kernel 4: click NN + fourier pos emb + gather ----------------
__global__ __launch_bounds__(256) void click_prep_kernel(
    const float* __restrict__ click_query, const float* __restrict__ enc_xyz,
    const float* __restrict__ enc_features, const float* __restrict__ pc_min,
    const float* __restrict__ pc_max, const float* __restrict__ gauss_B) {
    int m = blockIdx.x;          // b*NCK + c
    int b = m >> 6;
    int tid = threadIdx.x;
    float qx = click_query[m*3+0], qy = click_query[m*3+1], qz = click_query[m*3+2];

    const float* xyz = enc_xyz + (size_t)b*NPTS*3;
    float bestd = 3.4e38f; int besti = 0;
    for (int p = tid; p < NPTS; p += 256) {
        float dx = qx - xyz[p*3+0];
        float dy = qy - xyz[p*3+1];
        float dz = qz - xyz[p*3+2];
        float d2 = dx*dx + dy*dy + dz*dz;
        if (d2 < bestd) { bestd = d2; besti = p; }
    }
    __shared__ float sv[256];
    __shared__ int   si[256];
    sv[tid] = bestd; si[tid] = besti;
    __syncthreads();
    #pragma unroll
    for (int off = 128; off > 0; off >>= 1) {
        if (tid < off) {
            float v2 = sv[tid+off]; int j2 = si[tid+off];
            if (v2 < sv[tid] || (v2 == sv[tid] && j2 < si[tid])) { sv[tid] = v2; si[tid] = j2; }
        }
        __syncthreads();
    }
    int nn = si[0];
    // gather enc feature into first 256 cols
    g_Xclick[(size_t)m*(2*CDIM) + tid] = enc_features[((size_t)b*NPTS + nn)*CDIM + tid];
    // fourier pos emb into last 256 cols
    if (tid < 128) {
        float x0 = (qx - pc_min[b*3+0]) / (pc_max[b*3+0] - pc_min[b*3+0]);
        float y0 = (qy - pc_min[b*3+1]) / (pc_max[b*3+1] - pc_min[b*3+1]);
        float z0 = (qz - pc_min[b*3+2]) / (pc_max[b*3+2] - pc_min[b*3+2]);
        const float twopi = 6.283185307179586f;
        float proj = (x0*twopi)*gauss_B[tid] + (y0*twopi)*gauss_B[128+tid] + (z0*twopi)*gauss_B[256+tid];
        g_Xclick[(size_t)m*(2*CDIM) + CDIM + tid]       = sinf(proj);
        g_Xclick[(size_t)m*(2*CDIM) + CDIM + 128 + tid] = cosf(proj);
    }
}

// ---------------- tiled fp32 GEMM: C = act(A[M,K] @ B[K,N] + bias) ----------------
// mode 0: C row-major [M,N]
// mode 1: box final  -> out + m*6144 + (m>>6)*BOX_HALF
// mode 2: click final-> out + m*6144 + (m>>6)*BOX_HALF + BOX_HALF
__global__ __launch_bounds__(256) void gemm_tile_kernel(
    const float* __restrict__ A, const float* __restrict__ B,
    const float* __restrict__ bias, float* __restrict__ C,
    int M, int N, int K, int relu, int mode) {
    __shared__ float As[8][128];
    __shared__ float Bs[8][128];
    int bm = blockIdx.y * 128;
    int bn = blockIdx.x * 128;
    int tid = threadIdx.x;

    int a_row = tid >> 1;            // 0..127
    int a_k4  = (tid & 1) * 4;       // 0 or 4
    int b_row = tid >> 5;            // 0..7
    int b_col = (tid & 31) * 4;      // 0..124

    int ty = tid >> 4;               // 0..15
    int tx = tid & 15;               // 0..15
    int row0 = ty * 4;
    int col0 = tx * 4;

    float acc[8][8];
    #pragma unroll
    for (int i = 0; i < 8; i++)
        #pragma unroll
        for (int j = 0; j < 8; j++) acc[i][j] = 0.0f;

    for (int k0 = 0; k0 < K; k0 += 8) {
        float4 av = *(const float4*)&A[(size_t)(bm + a_row)*K + k0 + a_k4];
        As[a_k4+0][a_row] = av.x;
        As[a_k4+1][a_row] = av.y;
        As[a_k4+2][a_row] = av.z;
        As[a_k4+3][a_row] = av.w;
        float4 bv = *(const float4*)&B[(size_t)(k0 + b_row)*N + bn + b_col];
        *(float4*)&Bs[b_row][b_col] = bv;
        __syncthreads();
        #pragma unroll
        for (int kk = 0; kk < 8; kk++) {
            float a[8], bb[8];
            *(float4*)&a[0]  = *(float4*)&As[kk][row0];
            *(float4*)&a[4]  = *(float4*)&As[kk][row0 + 64];
            *(float4*)&bb[0] = *(float4*)&Bs[kk][col0];
            *(float4*)&bb[4] = *(float4*)&Bs[kk][col0 + 64];
            #pragma unroll
            for (int i = 0; i < 8; i++)
                #pragma unroll
                for (int j = 0; j < 8; j++)
                    acc[i][j] = fmaf(a[i], bb[j], acc[i][j]);
        }
        __syncthreads();
    }

    #pragma unroll
    for (int i = 0; i < 8; i++) {
        int r = (i < 4) ? (row0 + i) : (64 + row0 + i - 4);
        int m = bm + r;
        size_t rowbase;
        if (mode == 0) rowbase = (size_t)m * N;
        else {
            rowbase = (size_t)m * NOUT + (size_t)(m >> 6) * BOX_HALF;
            if (mode == 2) rowbase += BOX_HALF;
        }
        #pragma unroll
        for (int jh = 0; jh < 2; jh++) {
            int c0 = bn + col0 + jh * 64;
            float4 v;
            v.x = acc[i][jh*4+0] + bias[c0+0];
            v.y = acc[i][jh*4+1] + bias[c0+1];
            v.z = acc[i][jh*4+2] + bias[c0+2];
            v.w = acc[i][jh*4+3] + bias[c0+3];
            if (relu) {
                v.x = fmaxf(v.x, 0.0f); v.y = fmaxf(v.y, 0.0f);
                v.z = fmaxf(v.z, 0.0f); v.w = fmaxf(v.w, 0.0f);
            }
            *(float4*)&C[rowbase + c0] = v;
        }
    }
}

// ---------------- mask tail ----------------
__global__ void mask_fill_kernel(const float* __restrict__ box_qmask,
                                 const float* __restrict__ click_qmask,
                                 float* __restrict__ out) {
    int i = blockIdx.x * blockDim.x + threadIdx.x;
    if (i >= BATCH * (NBQ+NCK) * VQ) return;
    int b = i / ((NBQ+NCK)*VQ);
    int s = i % ((NBQ+NCK)*VQ);
    float v;
    if (s < NBQ*VQ) v = box_qmask[b*NBQ + (s >> 3)];
    else            v = click_qmask[b*NCK + ((s - NBQ*VQ) >> 3)];
    out[FEAT_TOTAL + i] = v;
}

// ---------------- launch ----------------
extern "C" void kernel_launch(void* const* d_in, const int* in_sizes, int n_in,
                              void* d_out, int out_size) {
    const float* sem_cls_logits = (const float*)d_in[0];
    const float* prop_features  = (const float*)d_in[1];
    const float* box_corners    = (const float*)d_in[2];
    const float* enc_xyz        = (const float*)d_in[3];
    const float* enc_features   = (const float*)d_in[4];
    const float* pc_min         = (const float*)d_in[5];
    const float* pc_max         = (const float*)d_in[6];
    const float* box_query      = (const float*)d_in[7];
    const float* box_qmask      = (const float*)d_in[8];
    const float* click_query    = (const float*)d_in[9];
    const float* click_qmask    = (const float*)d_in[10];
    const float* gauss_B        = (const float*)d_in[11];
    const float* box_w1         = (const float*)d_in[12];
    const float* box_b1         = (const float*)d_in[13];
    const float* box_w2         = (const float*)d_in[14];
    const float* box_b2         = (const float*)d_in[15];
    const float* click_w1       = (const float*)d_in[16];
    const float* click_b1       = (const float*)d_in[17];
    const float* click_w2       = (const float*)d_in[18];
    const float* click_b2       = (const float*)d_in[19];
    float* out = (float*)d_out;

    float *Xbox, *Xclick, *Hbox, *Hclick;
    cudaGetSymbolAddress((void**)&Xbox,   g_Xbox);
    cudaGetSymbolAddress((void**)&Xclick, g_Xclick);
    cudaGetSymbolAddress((void**)&Hbox,   g_Hbox);
    cudaGetSymbolAddress((void**)&Hclick, g_Hclick);

    prep_props_kernel<<<(BATCH*NPROP + 255)/256, 256>>>(sem_cls_logits, box_corners);
    prep_queries_kernel<<<(BATCH*NBQ + 255)/256, 256>>>(box_query);
    box_match_kernel<<<MROWS, 256>>>(prop_features);
    click_prep_kernel<<<MROWS, 256>>>(click_query, enc_xyz, enc_features,
                                      pc_min, pc_max, gauss_B);

    // GEMM1: X @ w1 + b1, relu
    {
        dim3 grid(QHD/128, MROWS/128);
        gemm_tile_kernel<<<grid, 256>>>(Xbox,   box_w1,   box_b1,   Hbox,
                                        MROWS, QHD, CDIM,   1, 0);
        gemm_tile_kernel<<<grid, 256>>>(Xclick, click_w1, click_b1, Hclick,
                                        MROWS, QHD, 2*CDIM, 1, 0);
    }
    // GEMM2: H @ w2 + b2 -> directly into output feature region
    {
        dim3 grid(NOUT/128, MROWS/128);
        gemm_tile_kernel<<<grid, 256>>>(Hbox,   box_w2,   box_b2,   out,
                                        MROWS, NOUT, QHD, 0, 1);
        gemm_tile_kernel<<<grid, 256>>>(Hclick, click_w2, click_b2, out,
                                        MROWS, NOUT, QHD, 0, 2);
    }
    mask_fill_kernel<<<(BATCH*(NBQ+NCK)*VQ + 255)/256, 256>>>(box_qmask, click_qmask, out);
}

// round 5
// speedup vs baseline: 1.7701x; 1.7701x over previous
#include <cuda_runtime.h>
#include <cuda_bf16.h>
#include <stdint.h>
#include <math.h>

// ---------------- problem constants ----------------
#define BATCH 32
#define NPROP 256
#define NCLS  19
#define NPTS  4096
#define NBQ   64
#define NCK   64
#define CDIM  256
#define QHD   768
#define VQ    8
#define NOUT  (VQ*QHD)                 // 6144
#define MROWS (BATCH*NBQ)              // 2048
#define FEAT_TOTAL ((size_t)BATCH*(NBQ+NCK)*VQ*QHD)
#define BOX_HALF   (NBQ*VQ*QHD)        // 393216

#define K2_BOX1  (3*CDIM)      // 768
#define K2_CLK1  (3*2*CDIM)    // 1536
#define K2_G2    (3*QHD)       // 2304

// ---------------- scratch ----------------
__device__ float g_mnp[BATCH*NPROP*3];
__device__ float g_mxp[BATCH*NPROP*3];
__device__ float g_volp[BATCH*NPROP];
__device__ float g_maskp[BATCH*NPROP];
__device__ float g_mnq[BATCH*NBQ*3];
__device__ float g_mxq[BATCH*NBQ*3];
__device__ float g_volq[BATCH*NBQ];

__device__ __align__(128) __nv_bfloat16 g_Xbox2  [(size_t)MROWS*K2_BOX1];
__device__ __align__(128) __nv_bfloat16 g_Xclick2[(size_t)MROWS*K2_CLK1];
__device__ __align__(128) __nv_bfloat16 g_Hbox2  [(size_t)MROWS*K2_G2];
__device__ __align__(128) __nv_bfloat16 g_Hclick2[(size_t)MROWS*K2_G2];
__device__ __align__(128) __nv_bfloat16 g_Wb1[(size_t)QHD*K2_BOX1];
__device__ __align__(128) __nv_bfloat16 g_Wc1[(size_t)QHD*K2_CLK1];
__device__ __align__(128) __nv_bfloat16 g_Wb2[(size_t)NOUT*K2_G2];
__device__ __align__(128) __nv_bfloat16 g_Wc2[(size_t)NOUT*K2_G2];

// ---------------- helpers ----------------
static __device__ __forceinline__ uint32_t smem_u32(const void* p) {
    uint32_t a;
    asm("{ .reg .u64 t; cvta.to.shared.u64 t, %1; cvt.u32.u64 %0, t; }" : "=r"(a) : "l"(p));
    return a;
}
#define CPA16(s, g) asm volatile("cp.async.cg.shared.global [%0], [%1], 16;\n" :: "r"(s), "l"(g))
#define CPA_COMMIT() asm volatile("cp.async.commit_group;\n" ::: "memory")

#define LDMX4(r, a) \
    asm volatile("ldmatrix.sync.aligned.m8n8.x4.shared.b16 {%0,%1,%2,%3}, [%4];" \
        : "=r"((r)[0]), "=r"((r)[1]), "=r"((r)[2]), "=r"((r)[3]) : "r"(a))

#define MMA16816(d, a, b0_, b1_) \
    asm volatile("mma.sync.aligned.m16n8k16.row.col.f32.bf16.bf16.f32 " \
        "{%0,%1,%2,%3}, {%4,%5,%6,%7}, {%8,%9}, {%0,%1,%2,%3};" \
        : "+f"((d)[0]), "+f"((d)[1]), "+f"((d)[2]), "+f"((d)[3]) \
        : "r"((a)[0]), "r"((a)[1]), "r"((a)[2]), "r"((a)[3]), "r"(b0_), "r"(b1_))

static __device__ __forceinline__ void split_bf16(float v, __nv_bfloat16& hi, __nv_bfloat16& lo) {
    hi = __float2bfloat16(v);
    lo = __float2bfloat16(v - __bfloat162float(hi));
}

// ---------------- prep kernels ----------------
__global__ void prep_props_kernel(const float* __restrict__ logits,
                                  const float* __restrict__ corners) {
    int i = blockIdx.x * blockDim.x + threadIdx.x;
    if (i >= BATCH*NPROP) return;
    const float* lg = logits + (size_t)i*NCLS;
    int am = 0; float best = lg[0];
    #pragma unroll
    for (int c = 1; c < NCLS; c++) { float v = lg[c]; if (v > best) { best = v; am = c; } }
    g_maskp[i] = (am != NCLS-1) ? 1.0f : 0.0f;
    const float* cr = corners + (size_t)i*24;
    float mn[3] = {cr[0], cr[1], cr[2]};
    float mx[3] = {cr[0], cr[1], cr[2]};
    #pragma unroll
    for (int k = 1; k < 8; k++)
        #pragma unroll
        for (int d = 0; d < 3; d++) {
            float v = cr[k*3+d];
            mn[d] = fminf(mn[d], v); mx[d] = fmaxf(mx[d], v);
        }
    float vol = 1.0f;
    #pragma unroll
    for (int d = 0; d < 3; d++) {
        g_mnp[i*3+d] = mn[d]; g_mxp[i*3+d] = mx[d];
        vol *= (mx[d] - mn[d]);
    }
    g_volp[i] = vol;
}

__global__ void prep_queries_kernel(const float* __restrict__ box_query) {
    int i = blockIdx.x * blockDim.x + threadIdx.x;
    if (i >= BATCH*NBQ) return;
    const float* cr = box_query + (size_t)i*24;
    float mn[3] = {cr[0], cr[1], cr[2]};
    float mx[3] = {cr[0], cr[1], cr[2]};
    #pragma unroll
    for (int k = 1; k < 8; k++)
        #pragma unroll
        for (int d = 0; d < 3; d++) {
            float v = cr[k*3+d];
            mn[d] = fminf(mn[d], v); mx[d] = fmaxf(mx[d], v);
        }
    float vol = 1.0f;
    #pragma unroll
    for (int d = 0; d < 3; d++) {
        g_mnq[i*3+d] = mn[d]; g_mxq[i*3+d] = mx[d];
        vol *= (mx[d] - mn[d]);
    }
    g_volq[i] = vol;
}

__global__ __launch_bounds__(256) void box_match_kernel(const float* __restrict__ prop_features) {
    int m = blockIdx.x;
    int b = m >> 6;
    int tid = threadIdx.x;
    float mnq0 = g_mnq[m*3+0], mnq1 = g_mnq[m*3+1], mnq2 = g_mnq[m*3+2];
    float mxq0 = g_mxq[m*3+0], mxq1 = g_mxq[m*3+1], mxq2 = g_mxq[m*3+2];
    float volq = g_volq[m];
    int pi = b*NPROP + tid;
    float i0 = fmaxf(fminf(mxq0, g_mxp[pi*3+0]) - fmaxf(mnq0, g_mnp[pi*3+0]), 0.0f);
    float i1 = fmaxf(fminf(mxq1, g_mxp[pi*3+1]) - fmaxf(mnq1, g_mnp[pi*3+1]), 0.0f);
    float i2 = fmaxf(fminf(mxq2, g_mxp[pi*3+2]) - fmaxf(mnq2, g_mnp[pi*3+2]), 0.0f);
    float inter = i0*i1*i2;
    float iou = inter / (volq + g_volp[pi] - inter + 1e-8f);
    iou *= g_maskp[pi];

    __shared__ float sv[256];
    __shared__ int   si[256];
    sv[tid] = iou; si[tid] = tid;
    __syncthreads();
    #pragma unroll
    for (int off = 128; off > 0; off >>= 1) {
        if (tid < off) {
            float v2 = sv[tid+off]; int j2 = si[tid+off];
            if (v2 > sv[tid] || (v2 == sv[tid] && j2 < si[tid])) { sv[tid] = v2; si[tid] = j2; }
        }
        __syncthreads();
    }
    int idx = si[0];
    float v = prop_features[((size_t)b*NPROP + idx)*CDIM + tid];
    __nv_bfloat16 hi, lo; split_bf16(v, hi, lo);
    size_t rb = (size_t)m*K2_BOX1;
    g_Xbox2[rb + tid] = hi;
    g_Xbox2[rb + CDIM + tid] = hi;
    g_Xbox2[rb + 2*CDIM + tid] = lo;
}

__global__ __launch_bounds__(256) void click_prep_kernel(
    const float* __restrict__ click_query, const float* __restrict__ enc_xyz,
    const float* __restrict__ enc_features, const float* __restrict__ pc_min,
    const float* __restrict__ pc_max, const float* __restrict__ gauss_B) {
    int m = blockIdx.x;
    int b = m >> 6;
    int tid = threadIdx.x;
    float qx = click_query[m*3+0], qy = click_query[m*3+1], qz = click_query[m*3+2];

    const float* xyz = enc_xyz + (size_t)b*NPTS*3;
    float bestd = 3.4e38f; int besti = 0;
    for (int p = tid; p < NPTS; p += 256) {
        float dx = qx - xyz[p*3+0];
        float dy = qy - xyz[p*3+1];
        float dz = qz - xyz[p*3+2];
        float d2 = dx*dx + dy*dy + dz*dz;
        if (d2 < bestd) { bestd = d2; besti = p; }
    }
    __shared__ float sv[256];
    __shared__ int   si[256];
    sv[tid] = bestd; si[tid] = besti;
    __syncthreads();
    #pragma unroll
    for (int off = 128; off > 0; off >>= 1) {
        if (tid < off) {
            float v2 = sv[tid+off]; int j2 = si[tid+off];
            if (v2 < sv[tid] || (v2 == sv[tid] && j2 < si[tid])) { sv[tid] = v2; si[tid] = j2; }
        }
        __syncthreads();
    }
    int nn = si[0];
    size_t rb = (size_t)m*K2_CLK1;
    {
        float v = enc_features[((size_t)b*NPTS + nn)*CDIM + tid];
        __nv_bfloat16 hi, lo; split_bf16(v, hi, lo);
        g_Xclick2[rb + tid] = hi;
        g_Xclick2[rb + 2*CDIM + tid] = hi;
        g_Xclick2[rb + 4*CDIM + tid] = lo;
    }
    if (tid < 128) {
        float x0 = (qx - pc_min[b*3+0]) / (pc_max[b*3+0] - pc_min[b*3+0]);
        float y0 = (qy - pc_min[b*3+1]) / (pc_max[b*3+1] - pc_min[b*3+1]);
        float z0 = (qz - pc_min[b*3+2]) / (pc_max[b*3+2] - pc_min[b*3+2]);
        const float twopi = 6.283185307179586f;
        float proj = (x0*twopi)*gauss_B[tid] + (y0*twopi)*gauss_B[128+tid] + (z0*twopi)*gauss_B[256+tid];
        float s = sinf(proj), c = cosf(proj);
        __nv_bfloat16 hs, ls, hc, lc;
        split_bf16(s, hs, ls); split_bf16(c, hc, lc);
        int cs = CDIM + tid, cc = CDIM + 128 + tid;
        g_Xclick2[rb + cs] = hs;             g_Xclick2[rb + cc] = hc;
        g_Xclick2[rb + 2*CDIM + cs] = hs;    g_Xclick2[rb + 2*CDIM + cc] = hc;
        g_Xclick2[rb + 4*CDIM + cs] = ls;    g_Xclick2[rb + 4*CDIM + cc] = lc;
    }
}

// ---------------- weight conversion: W[K,N] fp32 -> B''[N,3K] bf16 ----------------
__global__ __launch_bounds__(256) void conv_weight_kernel(
    const float* __restrict__ W, __nv_bfloat16* __restrict__ B2, int K, int N) {
    __shared__ float t[32][33];
    int n0 = blockIdx.x * 32, k0 = blockIdx.y * 32;
    int tx = threadIdx.x, ty = threadIdx.y;   // block (32,8)
    #pragma unroll
    for (int j = 0; j < 4; j++) {
        int k = k0 + ty + j*8;
        t[ty + j*8][tx] = W[(size_t)k*N + n0 + tx];
    }
    __syncthreads();
    #pragma unroll
    for (int j = 0; j < 4; j++) {
        int n = n0 + ty + j*8;
        int k = k0 + tx;
        float v = t[tx][ty + j*8];
        __nv_bfloat16 hi, lo; split_bf16(v, hi, lo);
        size_t rb = (size_t)n * (3*(size_t)K);
        B2[rb + k] = hi;
        B2[rb + K + k] = lo;
        B2[rb + 2*K + k] = hi;
    }
}

// ---------------- HMMA bf16 GEMM ----------------
// D[M,N] = A''[M,K2] x B''[N,K2]^T, CTA tile 128x128, BK=64, 3-stage cp.async.
// mode 0: relu(d+bias) -> triple bf16 split into outB [M,2304]
// mode 1: d+bias -> outF + m*6144 + (m>>6)*BOX_HALF
// mode 2: same + BOX_HALF
#define BM 128
#define BN 128
#define STAGE_BYTES 32768      // A 16KB + B 16KB
#define OFF_STAGE 512
#define GEMM_SMEM (OFF_STAGE + 3*STAGE_BYTES)   // 98816

static __device__ __forceinline__ void load_chunk(
    const __nv_bfloat16* A2, const __nv_bfloat16* B2, int K2,
    int bm, int bn, int c, uint32_t sbase, int stage)
{
    int t = threadIdx.x;
    int r = t >> 1;              // 0..127
    int c0 = (t & 1) * 4;        // 0 or 4
    uint32_t stA = sbase + OFF_STAGE + stage*STAGE_BYTES;
    uint32_t stB = stA + 16384;
    const char* ga = (const char*)(A2 + (size_t)(bm + r)*K2 + c*64);
    const char* gb = (const char*)(B2 + (size_t)(bn + r)*K2 + c*64);
    uint32_t rowoff = (uint32_t)r * 128;
    int sw = r & 7;
    #pragma unroll
    for (int i = 0; i < 4; i++) {
        int ch = c0 + i;
        uint32_t off = rowoff + (uint32_t)((ch ^ sw) << 4);
        CPA16(stA + off, ga + (ch << 4));
        CPA16(stB + off, gb + (ch << 4));
    }
}

__global__ __launch_bounds__(256, 2) void gemm_hmma_kernel(
    const __nv_bfloat16* A0, const __nv_bfloat16* B0, const float* bias0,
    const __nv_bfloat16* A1, const __nv_bfloat16* B1, const float* bias1,
    int k20, int k21, int mode0_, int mode1_,
    float* outF, __nv_bfloat16* outB0, __nv_bfloat16* outB1)
{
    extern __shared__ char smem[];
    const int z = blockIdx.z;
    const __nv_bfloat16* A2 = z ? A1 : A0;
    const __nv_bfloat16* B2 = z ? B1 : B0;
    const float* bias = z ? bias1 : bias0;
    __nv_bfloat16* outB = z ? outB1 : outB0;
    const int K2 = z ? k21 : k20;
    const int mode = z ? mode1_ : mode0_;
    const int bm = blockIdx.y * BM, bn = blockIdx.x * BN;
    const int tid = threadIdx.x, wid = tid >> 5, lane = tid & 31;
    const int warp_m = wid >> 2, warp_n = wid & 3;
    uint32_t sbase = smem_u32(smem);
    float* sBias = (float*)smem;
    if (tid < 128) sBias[tid] = bias[bn + tid];

    float acc[4][4][4];
    #pragma unroll
    for (int mi = 0; mi < 4; mi++)
        #pragma unroll
        for (int nj = 0; nj < 4; nj++)
            #pragma unroll
            for (int e = 0; e < 4; e++) acc[mi][nj][e] = 0.0f;

    const int nch = K2 >> 6;
    load_chunk(A2, B2, K2, bm, bn, 0, sbase, 0); CPA_COMMIT();
    load_chunk(A2, B2, K2, bm, bn, 1, sbase, 1); CPA_COMMIT();
    load_chunk(A2, B2, K2, bm, bn, 2, sbase, 2); CPA_COMMIT();

    const int lane15 = lane & 15, s7 = lane & 7, hic = lane >> 4;

    for (int c = 0; c < nch; c++) {
        int s = c - (c/3)*3;
        if (c + 3 < nch) { asm volatile("cp.async.wait_group 2;\n" ::: "memory"); }
        else             { asm volatile("cp.async.wait_group 0;\n" ::: "memory"); }
        __syncthreads();

        uint32_t stA = sbase + OFF_STAGE + s*STAGE_BYTES;
        uint32_t stB = stA + 16384;
        uint32_t aBase[4], bBase[2];
        #pragma unroll
        for (int mi = 0; mi < 4; mi++)
            aBase[mi] = stA + (uint32_t)(warp_m*64 + mi*16 + lane15) * 128;
        #pragma unroll
        for (int nt = 0; nt < 2; nt++)
            bBase[nt] = stB + (uint32_t)(warp_n*32 + nt*16 + lane15) * 128;

        #pragma unroll
        for (int ks = 0; ks < 4; ks++) {
            uint32_t coff = (uint32_t)(((2*ks + hic) ^ s7) << 4);
            uint32_t afr[4][4], bfr[2][4];
            #pragma unroll
            for (int mi = 0; mi < 4; mi++) LDMX4(afr[mi], aBase[mi] + coff);
            #pragma unroll
            for (int nt = 0; nt < 2; nt++) LDMX4(bfr[nt], bBase[nt] + coff);
            #pragma unroll
            for (int mi = 0; mi < 4; mi++)
                #pragma unroll
                for (int nj = 0; nj < 4; nj++)
                    MMA16816(acc[mi][nj], afr[mi],
                             bfr[nj>>1][nj&1], bfr[nj>>1][2 + (nj&1)]);
        }
        __syncthreads();
        if (c + 3 < nch) {
            load_chunk(A2, B2, K2, bm, bn, c + 3, sbase, s);
            CPA_COMMIT();
        }
    }

    // ---- epilogue ----
    #pragma unroll
    for (int mi = 0; mi < 4; mi++) {
        int rr0 = warp_m*64 + mi*16 + (lane >> 2);
        #pragma unroll
        for (int h = 0; h < 2; h++) {
            int m = bm + rr0 + 8*h;
            size_t rowbase;
            if (mode == 0) rowbase = (size_t)m * K2_G2;
            else {
                rowbase = (size_t)m * NOUT + (size_t)(m >> 6) * BOX_HALF;
                if (mode == 2) rowbase += BOX_HALF;
            }
            #pragma unroll
            for (int nj = 0; nj < 4; nj++) {
                int cc = warp_n*32 + nj*8 + 2*(lane & 3);
                float v0 = acc[mi][nj][2*h+0] + sBias[cc];
                float v1 = acc[mi][nj][2*h+1] + sBias[cc+1];
                if (mode == 0) {
                    v0 = fmaxf(v0, 0.0f); v1 = fmaxf(v1, 0.0f);
                    __nv_bfloat16 h0, l0, h1, l1;
                    split_bf16(v0, h0, l0); split_bf16(v1, h1, l1);
                    __nv_bfloat162 hp; hp.x = h0; hp.y = h1;
                    __nv_bfloat162 lp; lp.x = l0; lp.y = l1;
                    size_t col = (size_t)(bn + cc);
                    *(__nv_bfloat162*)&outB[rowbase + col] = hp;
                    *(__nv_bfloat162*)&outB[rowbase + QHD + col] = hp;
                    *(__nv_bfloat162*)&outB[rowbase + 2*QHD + col] = lp;
                } else {
                    float2 v; v.x = v0; v.y = v1;
                    *(float2*)&outF[rowbase + bn + cc] = v;
                }
            }
        }
    }
}

// ---------------- mask tail ----------------
__global__ void mask_fill_kernel(const float* __restrict__ box_qmask,
                                 const float* __restrict__ click_qmask,
                                 float* __restrict__ out) {
    int i = blockIdx.x * blockDim.x + threadIdx.x;
    if (i >= BATCH * (NBQ+NCK) * VQ) return;
    int b = i / ((NBQ+NCK)*VQ);
    int s = i % ((NBQ+NCK)*VQ);
    float v;
    if (s < NBQ*VQ) v = box_qmask[b*NBQ + (s >> 3)];
    else            v = click_qmask[b*NCK + ((s - NBQ*VQ) >> 3)];
    out[FEAT_TOTAL + i] = v;
}

// ---------------- launch ----------------
extern "C" void kernel_launch(void* const* d_in, const int* in_sizes, int n_in,
                              void* d_out, int out_size) {
    const float* sem_cls_logits = (const float*)d_in[0];
    const float* prop_features  = (const float*)d_in[1];
    const float* box_corners    = (const float*)d_in[2];
    const float* enc_xyz        = (const float*)d_in[3];
    const float* enc_features   = (const float*)d_in[4];
    const float* pc_min         = (const float*)d_in[5];
    const float* pc_max         = (const float*)d_in[6];
    const float* box_query      = (const float*)d_in[7];
    const float* box_qmask      = (const float*)d_in[8];
    const float* click_query    = (const float*)d_in[9];
    const float* click_qmask    = (const float*)d_in[10];
    const float* gauss_B        = (const float*)d_in[11];
    const float* box_w1         = (const float*)d_in[12];
    const float* box_b1         = (const float*)d_in[13];
    const float* box_w2         = (const float*)d_in[14];
    const float* box_b2         = (const float*)d_in[15];
    const float* click_w1       = (const float*)d_in[16];
    const float* click_b1       = (const float*)d_in[17];
    const float* click_w2       = (const float*)d_in[18];
    const float* click_b2       = (const float*)d_in[19];
    float* out = (float*)d_out;

    __nv_bfloat16 *Xb2, *Xc2, *Hb2, *Hc2, *Wb1, *Wc1, *Wb2, *Wc2;
    cudaGetSymbolAddress((void**)&Xb2, g_Xbox2);
    cudaGetSymbolAddress((void**)&Xc2, g_Xclick2);
    cudaGetSymbolAddress((void**)&Hb2, g_Hbox2);
    cudaGetSymbolAddress((void**)&Hc2, g_Hclick2);
    cudaGetSymbolAddress((void**)&Wb1, g_Wb1);
    cudaGetSymbolAddress((void**)&Wc1, g_Wc1);
    cudaGetSymbolAddress((void**)&Wb2, g_Wb2);
    cudaGetSymbolAddress((void**)&Wc2, g_Wc2);

    cudaFuncSetAttribute(gemm_hmma_kernel,
                         cudaFuncAttributeMaxDynamicSharedMemorySize, GEMM_SMEM);

    // prep
    prep_props_kernel<<<(BATCH*NPROP + 255)/256, 256>>>(sem_cls_logits, box_corners);
    prep_queries_kernel<<<(BATCH*NBQ + 255)/256, 256>>>(box_query);
    box_match_kernel<<<MROWS, 256>>>(prop_features);
    click_prep_kernel<<<MROWS, 256>>>(click_query, enc_xyz, enc_features,
                                      pc_min, pc_max, gauss_B);
    // weight conversion (W[K,N] fp32 -> [N,3K] bf16)
    {
        dim3 blk(32, 8);
        conv_weight_kernel<<<dim3(QHD/32, CDIM/32),   blk>>>(box_w1,   Wb1, CDIM,   QHD);
        conv_weight_kernel<<<dim3(QHD/32, 2*CDIM/32), blk>>>(click_w1, Wc1, 2*CDIM, QHD);
        conv_weight_kernel<<<dim3(NOUT/32, QHD/32),   blk>>>(box_w2,   Wb2, QHD,    NOUT);
        conv_weight_kernel<<<dim3(NOUT/32, QHD/32),   blk>>>(click_w2, Wc2, QHD,    NOUT);
    }
    // GEMM1 (both branches): X'' @ W1'' + b1, relu -> H'' (triple bf16)
    gemm_hmma_kernel<<<dim3(QHD/BN, MROWS/BM, 2), 256, GEMM_SMEM>>>(
        Xb2, Wb1, box_b1, Xc2, Wc1, click_b1,
        K2_BOX1, K2_CLK1, 0, 0, nullptr, Hb2, Hc2);
    // GEMM2 (both branches): H'' @ W2'' + b2 -> out (interleaved layout)
    gemm_hmma_kernel<<<dim3(NOUT/BN, MROWS/BM, 2), 256, GEMM_SMEM>>>(
        Hb2, Wb2, box_b2, Hc2, Wc2, click_b2,
        K2_G2, K2_G2, 1, 2, out, nullptr, nullptr);

    mask_fill_kernel<<<(BATCH*(NBQ+NCK)*VQ + 255)/256, 256>>>(box_qmask, click_qmask, out);
}

// round 6
// speedup vs baseline: 2.5217x; 1.4246x over previous
#include <cuda_runtime.h>
#include <cuda_fp16.h>
#include <stdint.h>
#include <math.h>

// ---------------- problem constants ----------------
#define BATCH 32
#define NPROP 256
#define NCLS  19
#define NPTS  4096
#define NBQ   64
#define NCK   64
#define CDIM  256
#define QHD   768
#define VQ    8
#define NOUT  (VQ*QHD)                 // 6144
#define MROWS (BATCH*NBQ)              // 2048
#define FEAT_TOTAL ((size_t)BATCH*(NBQ+NCK)*VQ*QHD)
#define BOX_HALF   (NBQ*VQ*QHD)        // 393216

// A-side K (2 segments: hi|lo)
#define K2_BOX1  (2*CDIM)      // 512
#define K2_CLK1  (2*2*CDIM)    // 1024
#define K2_G2    (2*QHD)       // 1536

// ---------------- scratch ----------------
__device__ float g_mnp[BATCH*NPROP*3];
__device__ float g_mxp[BATCH*NPROP*3];
__device__ float g_volp[BATCH*NPROP];
__device__ float g_maskp[BATCH*NPROP];
__device__ float g_mnq[BATCH*NBQ*3];
__device__ float g_mxq[BATCH*NBQ*3];
__device__ float g_volq[BATCH*NBQ];

__device__ __align__(128) __half g_Xbox2  [(size_t)MROWS*K2_BOX1];
__device__ __align__(128) __half g_Xclick2[(size_t)MROWS*K2_CLK1];
__device__ __align__(128) __half g_Hbox2  [(size_t)MROWS*K2_G2];
__device__ __align__(128) __half g_Hclick2[(size_t)MROWS*K2_G2];
__device__ __align__(128) __half g_Wb1[(size_t)QHD*CDIM];
__device__ __align__(128) __half g_Wc1[(size_t)QHD*2*CDIM];
__device__ __align__(128) __half g_Wb2[(size_t)NOUT*QHD];
__device__ __align__(128) __half g_Wc2[(size_t)NOUT*QHD];

// ---------------- helpers ----------------
static __device__ __forceinline__ uint32_t smem_u32(const void* p) {
    uint32_t a;
    asm("{ .reg .u64 t; cvta.to.shared.u64 t, %1; cvt.u32.u64 %0, t; }" : "=r"(a) : "l"(p));
    return a;
}
#define CPA16(s, g) asm volatile("cp.async.cg.shared.global [%0], [%1], 16;\n" :: "r"(s), "l"(g))
#define CPA_COMMIT() asm volatile("cp.async.commit_group;\n" ::: "memory")

#define LDMX4(r, a) \
    asm volatile("ldmatrix.sync.aligned.m8n8.x4.shared.b16 {%0,%1,%2,%3}, [%4];" \
        : "=r"((r)[0]), "=r"((r)[1]), "=r"((r)[2]), "=r"((r)[3]) : "r"(a))

#define MMA16816(d, a, b0_, b1_) \
    asm volatile("mma.sync.aligned.m16n8k16.row.col.f32.f16.f16.f32 " \
        "{%0,%1,%2,%3}, {%4,%5,%6,%7}, {%8,%9}, {%0,%1,%2,%3};" \
        : "+f"((d)[0]), "+f"((d)[1]), "+f"((d)[2]), "+f"((d)[3]) \
        : "r"((a)[0]), "r"((a)[1]), "r"((a)[2]), "r"((a)[3]), "r"(b0_), "r"(b1_))

static __device__ __forceinline__ void split_f16(float v, __half& hi, __half& lo) {
    hi = __float2half(v);
    lo = __float2half(v - __half2float(hi));
}

// ---------------- prep kernels ----------------
__global__ void prep_props_kernel(const float* __restrict__ logits,
                                  const float* __restrict__ corners) {
    int i = blockIdx.x * blockDim.x + threadIdx.x;
    if (i >= BATCH*NPROP) return;
    const float* lg = logits + (size_t)i*NCLS;
    int am = 0; float best = lg[0];
    #pragma unroll
    for (int c = 1; c < NCLS; c++) { float v = lg[c]; if (v > best) { best = v; am = c; } }
    g_maskp[i] = (am != NCLS-1) ? 1.0f : 0.0f;
    const float* cr = corners + (size_t)i*24;
    float mn[3] = {cr[0], cr[1], cr[2]};
    float mx[3] = {cr[0], cr[1], cr[2]};
    #pragma unroll
    for (int k = 1; k < 8; k++)
        #pragma unroll
        for (int d = 0; d < 3; d++) {
            float v = cr[k*3+d];
            mn[d] = fminf(mn[d], v); mx[d] = fmaxf(mx[d], v);
        }
    float vol = 1.0f;
    #pragma unroll
    for (int d = 0; d < 3; d++) {
        g_mnp[i*3+d] = mn[d]; g_mxp[i*3+d] = mx[d];
        vol *= (mx[d] - mn[d]);
    }
    g_volp[i] = vol;
}

__global__ void prep_queries_kernel(const float* __restrict__ box_query) {
    int i = blockIdx.x * blockDim.x + threadIdx.x;
    if (i >= BATCH*NBQ) return;
    const float* cr = box_query + (size_t)i*24;
    float mn[3] = {cr[0], cr[1], cr[2]};
    float mx[3] = {cr[0], cr[1], cr[2]};
    #pragma unroll
    for (int k = 1; k < 8; k++)
        #pragma unroll
        for (int d = 0; d < 3; d++) {
            float v = cr[k*3+d];
            mn[d] = fminf(mn[d], v); mx[d] = fmaxf(mx[d], v);
        }
    float vol = 1.0f;
    #pragma unroll
    for (int d = 0; d < 3; d++) {
        g_mnq[i*3+d] = mn[d]; g_mxq[i*3+d] = mx[d];
        vol *= (mx[d] - mn[d]);
    }
    g_volq[i] = vol;
}

__global__ __launch_bounds__(256) void box_match_kernel(const float* __restrict__ prop_features) {
    int m = blockIdx.x;
    int b = m >> 6;
    int tid = threadIdx.x;
    float mnq0 = g_mnq[m*3+0], mnq1 = g_mnq[m*3+1], mnq2 = g_mnq[m*3+2];
    float mxq0 = g_mxq[m*3+0], mxq1 = g_mxq[m*3+1], mxq2 = g_mxq[m*3+2];
    float volq = g_volq[m];
    int pi = b*NPROP + tid;
    float i0 = fmaxf(fminf(mxq0, g_mxp[pi*3+0]) - fmaxf(mnq0, g_mnp[pi*3+0]), 0.0f);
    float i1 = fmaxf(fminf(mxq1, g_mxp[pi*3+1]) - fmaxf(mnq1, g_mnp[pi*3+1]), 0.0f);
    float i2 = fmaxf(fminf(mxq2, g_mxp[pi*3+2]) - fmaxf(mnq2, g_mnp[pi*3+2]), 0.0f);
    float inter = i0*i1*i2;
    float iou = inter / (volq + g_volp[pi] - inter + 1e-8f);
    iou *= g_maskp[pi];

    __shared__ float sv[256];
    __shared__ int   si[256];
    sv[tid] = iou; si[tid] = tid;
    __syncthreads();
    #pragma unroll
    for (int off = 128; off > 0; off >>= 1) {
        if (tid < off) {
            float v2 = sv[tid+off]; int j2 = si[tid+off];
            if (v2 > sv[tid] || (v2 == sv[tid] && j2 < si[tid])) { sv[tid] = v2; si[tid] = j2; }
        }
        __syncthreads();
    }
    int idx = si[0];
    float v = prop_features[((size_t)b*NPROP + idx)*CDIM + tid];
    __half hi, lo; split_f16(v, hi, lo);
    size_t rb = (size_t)m*K2_BOX1;
    g_Xbox2[rb + tid] = hi;
    g_Xbox2[rb + CDIM + tid] = lo;
}

__global__ __launch_bounds__(256) void click_prep_kernel(
    const float* __restrict__ click_query, const float* __restrict__ enc_xyz,
    const float* __restrict__ enc_features, const float* __restrict__ pc_min,
    const float* __restrict__ pc_max, const float* __restrict__ gauss_B) {
    int m = blockIdx.x;
    int b = m >> 6;
    int tid = threadIdx.x;
    float qx = click_query[m*3+0], qy = click_query[m*3+1], qz = click_query[m*3+2];

    const float* xyz = enc_xyz + (size_t)b*NPTS*3;
    float bestd = 3.4e38f; int besti = 0;
    for (int p = tid; p < NPTS; p += 256) {
        float dx = qx - xyz[p*3+0];
        float dy = qy - xyz[p*3+1];
        float dz = qz - xyz[p*3+2];
        float d2 = dx*dx + dy*dy + dz*dz;
        if (d2 < bestd) { bestd = d2; besti = p; }
    }
    __shared__ float sv[256];
    __shared__ int   si[256];
    sv[tid] = bestd; si[tid] = besti;
    __syncthreads();
    #pragma unroll
    for (int off = 128; off > 0; off >>= 1) {
        if (tid < off) {
            float v2 = sv[tid+off]; int j2 = si[tid+off];
            if (v2 < sv[tid] || (v2 == sv[tid] && j2 < si[tid])) { sv[tid] = v2; si[tid] = j2; }
        }
        __syncthreads();
    }
    int nn = si[0];
    size_t rb = (size_t)m*K2_CLK1;
    {
        float v = enc_features[((size_t)b*NPTS + nn)*CDIM + tid];
        __half hi, lo; split_f16(v, hi, lo);
        g_Xclick2[rb + tid] = hi;              // hi segment cols [0,512)
        g_Xclick2[rb + 2*CDIM + tid] = lo;     // lo segment cols [512,1024)
    }
    if (tid < 128) {
        float x0 = (qx - pc_min[b*3+0]) / (pc_max[b*3+0] - pc_min[b*3+0]);
        float y0 = (qy - pc_min[b*3+1]) / (pc_max[b*3+1] - pc_min[b*3+1]);
        float z0 = (qz - pc_min[b*3+2]) / (pc_max[b*3+2] - pc_min[b*3+2]);
        const float twopi = 6.283185307179586f;
        float proj = (x0*twopi)*gauss_B[tid] + (y0*twopi)*gauss_B[128+tid] + (z0*twopi)*gauss_B[256+tid];
        float s = sinf(proj), c = cosf(proj);
        __half hs, ls, hc, lc;
        split_f16(s, hs, ls); split_f16(c, hc, lc);
        int cs = CDIM + tid, cc = CDIM + 128 + tid;
        g_Xclick2[rb + cs] = hs;             g_Xclick2[rb + cc] = hc;
        g_Xclick2[rb + 2*CDIM + cs] = ls;    g_Xclick2[rb + 2*CDIM + cc] = lc;
    }
}

// ---------------- weight conversion: W[K,N] fp32 -> Wh[N,K] fp16 ----------------
__global__ __launch_bounds__(256) void conv_weight_kernel(
    const float* __restrict__ W, __half* __restrict__ B2, int K, int N) {
    __shared__ float t[32][33];
    int n0 = blockIdx.x * 32, k0 = blockIdx.y * 32;
    int tx = threadIdx.x, ty = threadIdx.y;   // block (32,8)
    #pragma unroll
    for (int j = 0; j < 4; j++) {
        int k = k0 + ty + j*8;
        t[ty + j*8][tx] = W[(size_t)k*N + n0 + tx];
    }
    __syncthreads();
    #pragma unroll
    for (int j = 0; j < 4; j++) {
        int n = n0 + ty + j*8;
        int k = k0 + tx;
        B2[(size_t)n*K + k] = __float2half(t[tx][ty + j*8]);
    }
}

// ---------------- HMMA fp16 GEMM ----------------
// D[M,N] = A''[M,K2] x B[N,KB]^T with B chunk index wrapping (K2 = 2*KB).
// CTA tile 128x128, BK=64, 3-stage cp.async pipeline.
// mode 0: relu(d+bias) -> fp16 hi/lo split into outB [M, 2*QHD]
// mode 1: d+bias -> outF + m*6144 + (m>>6)*BOX_HALF
// mode 2: same + BOX_HALF
#define BM 128
#define BN 128
#define STAGE_BYTES 32768      // A 16KB + B 16KB
#define OFF_STAGE 512
#define GEMM_SMEM (OFF_STAGE + 3*STAGE_BYTES)   // 98816

static __device__ __forceinline__ void load_chunk(
    const __half* A2, const __half* B2, int K2, int KB,
    int bm, int bn, int cA, int cB, uint32_t sbase, int stage)
{
    int t = threadIdx.x;
    int r = t >> 1;              // 0..127
    int c0 = (t & 1) * 4;        // 0 or 4
    uint32_t stA = sbase + OFF_STAGE + stage*STAGE_BYTES;
    uint32_t stB = stA + 16384;
    const char* ga = (const char*)(A2 + (size_t)(bm + r)*K2 + cA*64);
    const char* gb = (const char*)(B2 + (size_t)(bn + r)*KB + cB*64);
    uint32_t rowoff = (uint32_t)r * 128;
    int sw = r & 7;
    #pragma unroll
    for (int i = 0; i < 4; i++) {
        int ch = c0 + i;
        uint32_t off = rowoff + (uint32_t)((ch ^ sw) << 4);
        CPA16(stA + off, ga + (ch << 4));
        CPA16(stB + off, gb + (ch << 4));
    }
}

__global__ __launch_bounds__(256, 2) void gemm_hmma_kernel(
    const __half* A0, const __half* B0, const float* bias0,
    const __half* A1, const __half* B1, const float* bias1,
    int k20, int kb0, int k21, int kb1, int mode0_, int mode1_,
    float* outF, __half* outB0, __half* outB1)
{
    extern __shared__ char smem[];
    const int z = blockIdx.z;
    const __half* A2 = z ? A1 : A0;
    const __half* B2 = z ? B1 : B0;
    const float* bias = z ? bias1 : bias0;
    __half* outB = z ? outB1 : outB0;
    const int K2 = z ? k21 : k20;
    const int KB = z ? kb1 : kb0;
    const int mode = z ? mode1_ : mode0_;
    const int bm = blockIdx.y * BM, bn = blockIdx.x * BN;
    const int tid = threadIdx.x, wid = tid >> 5, lane = tid & 31;
    const int warp_m = wid >> 2, warp_n = wid & 3;
    uint32_t sbase = smem_u32(smem);
    float* sBias = (float*)smem;
    if (tid < 128) sBias[tid] = bias[bn + tid];

    float acc[4][4][4];
    #pragma unroll
    for (int mi = 0; mi < 4; mi++)
        #pragma unroll
        for (int nj = 0; nj < 4; nj++)
            #pragma unroll
            for (int e = 0; e < 4; e++) acc[mi][nj][e] = 0.0f;

    const int nch = K2 >> 6;          // A chunks
    const int nchB = KB >> 6;         // B chunks (= nch/2), index wraps
    #define CBIDX(c) ((c) >= nchB ? (c) - nchB : (c))
    load_chunk(A2, B2, K2, KB, bm, bn, 0, CBIDX(0), sbase, 0); CPA_COMMIT();
    load_chunk(A2, B2, K2, KB, bm, bn, 1, CBIDX(1), sbase, 1); CPA_COMMIT();
    load_chunk(A2, B2, K2, KB, bm, bn, 2, CBIDX(2), sbase, 2); CPA_COMMIT();

    const int lane15 = lane & 15, s7 = lane & 7, hic = lane >> 4;

    for (int c = 0; c < nch; c++) {
        int s = c - (c/3)*3;
        if (c + 3 < nch) { asm volatile("cp.async.wait_group 2;\n" ::: "memory"); }
        else             { asm volatile("cp.async.wait_group 0;\n" ::: "memory"); }
        __syncthreads();

        uint32_t stA = sbase + OFF_STAGE + s*STAGE_BYTES;
        uint32_t stB = stA + 16384;
        uint32_t aBase[4], bBase[2];
        #pragma unroll
        for (int mi = 0; mi < 4; mi++)
            aBase[mi] = stA + (uint32_t)(warp_m*64 + mi*16 + lane15) * 128;
        #pragma unroll
        for (int nt = 0; nt < 2; nt++)
            bBase[nt] = stB + (uint32_t)(warp_n*32 + nt*16 + lane15) * 128;

        #pragma unroll
        for (int ks = 0; ks < 4; ks++) {
            uint32_t coff = (uint32_t)(((2*ks + hic) ^ s7) << 4);
            uint32_t afr[4][4], bfr[2][4];
            #pragma unroll
            for (int mi = 0; mi < 4; mi++) LDMX4(afr[mi], aBase[mi] + coff);
            #pragma unroll
            for (int nt = 0; nt < 2; nt++) LDMX4(bfr[nt], bBase[nt] + coff);
            #pragma unroll
            for (int mi = 0; mi < 4; mi++)
                #pragma unroll
                for (int nj = 0; nj < 4; nj++)
                    MMA16816(acc[mi][nj], afr[mi],
                             bfr[nj>>1][nj&1], bfr[nj>>1][2 + (nj&1)]);
        }
        __syncthreads();
        if (c + 3 < nch) {
            int cn = c + 3;
            load_chunk(A2, B2, K2, KB, bm, bn, cn, CBIDX(cn), sbase, s);
            CPA_COMMIT();
        }
    }

    // ---- epilogue ----
    #pragma unroll
    for (int mi = 0; mi < 4; mi++) {
        int rr0 = warp_m*64 + mi*16 + (lane >> 2);
        #pragma unroll
        for (int h = 0; h < 2; h++) {
            int m = bm + rr0 + 8*h;
            size_t rowbase;
            if (mode == 0) rowbase = (size_t)m * K2_G2;
            else {
                rowbase = (size_t)m * NOUT + (size_t)(m >> 6) * BOX_HALF;
                if (mode == 2) rowbase += BOX_HALF;
            }
            #pragma unroll
            for (int nj = 0; nj < 4; nj++) {
                int cc = warp_n*32 + nj*8 + 2*(lane & 3);
                float v0 = acc[mi][nj][2*h+0] + sBias[cc];
                float v1 = acc[mi][nj][2*h+1] + sBias[cc+1];
                if (mode == 0) {
                    v0 = fmaxf(v0, 0.0f); v1 = fmaxf(v1, 0.0f);
                    __half h0, l0, h1, l1;
                    split_f16(v0, h0, l0); split_f16(v1, h1, l1);
                    __half2 hp; hp.x = h0; hp.y = h1;
                    __half2 lp; lp.x = l0; lp.y = l1;
                    size_t col = (size_t)(bn + cc);
                    *(__half2*)&outB[rowbase + col] = hp;
                    *(__half2*)&outB[rowbase + QHD + col] = lp;
                } else {
                    float2 v; v.x = v0; v.y = v1;
                    *(float2*)&outF[rowbase + bn + cc] = v;
                }
            }
        }
    }
}

// ---------------- mask tail ----------------
__global__ void mask_fill_kernel(const float* __restrict__ box_qmask,
                                 const float* __restrict__ click_qmask,
                                 float* __restrict__ out) {
    int i = blockIdx.x * blockDim.x + threadIdx.x;
    if (i >= BATCH * (NBQ+NCK) * VQ) return;
    int b = i / ((NBQ+NCK)*VQ);
    int s = i % ((NBQ+NCK)*VQ);
    float v;
    if (s < NBQ*VQ) v = box_qmask[b*NBQ + (s >> 3)];
    else            v = click_qmask[b*NCK + ((s - NBQ*VQ) >> 3)];
    out[FEAT_TOTAL + i] = v;
}

// ---------------- launch ----------------
extern "C" void kernel_launch(void* const* d_in, const int* in_sizes, int n_in,
                              void* d_out, int out_size) {
    const float* sem_cls_logits = (const float*)d_in[0];
    const float* prop_features  = (const float*)d_in[1];
    const float* box_corners    = (const float*)d_in[2];
    const float* enc_xyz        = (const float*)d_in[3];
    const float* enc_features   = (const float*)d_in[4];
    const float* pc_min         = (const float*)d_in[5];
    const float* pc_max         = (const float*)d_in[6];
    const float* box_query      = (const float*)d_in[7];
    const float* box_qmask      = (const float*)d_in[8];
    const float* click_query    = (const float*)d_in[9];
    const float* click_qmask    = (const float*)d_in[10];
    const float* gauss_B        = (const float*)d_in[11];
    const float* box_w1         = (const float*)d_in[12];
    const float* box_b1         = (const float*)d_in[13];
    const float* box_w2         = (const float*)d_in[14];
    const float* box_b2         = (const float*)d_in[15];
    const float* click_w1       = (const float*)d_in[16];
    const float* click_b1       = (const float*)d_in[17];
    const float* click_w2       = (const float*)d_in[18];
    const float* click_b2       = (const float*)d_in[19];
    float* out = (float*)d_out;

    __half *Xb2, *Xc2, *Hb2, *Hc2, *Wb1, *Wc1, *Wb2, *Wc2;
    cudaGetSymbolAddress((void**)&Xb2, g_Xbox2);
    cudaGetSymbolAddress((void**)&Xc2, g_Xclick2);
    cudaGetSymbolAddress((void**)&Hb2, g_Hbox2);
    cudaGetSymbolAddress((void**)&Hc2, g_Hclick2);
    cudaGetSymbolAddress((void**)&Wb1, g_Wb1);
    cudaGetSymbolAddress((void**)&Wc1, g_Wc1);
    cudaGetSymbolAddress((void**)&Wb2, g_Wb2);
    cudaGetSymbolAddress((void**)&Wc2, g_Wc2);

    cudaFuncSetAttribute(gemm_hmma_kernel,
                         cudaFuncAttributeMaxDynamicSharedMemorySize, GEMM_SMEM);

    // prep
    prep_props_kernel<<<(BATCH*NPROP + 255)/256, 256>>>(sem_cls_logits, box_corners);
    prep_queries_kernel<<<(BATCH*NBQ + 255)/256, 256>>>(box_query);
    box_match_kernel<<<MROWS, 256>>>(prop_features);
    click_prep_kernel<<<MROWS, 256>>>(click_query, enc_xyz, enc_features,
                                      pc_min, pc_max, gauss_B);
    // weight conversion (W[K,N] fp32 -> Wh[N,K] fp16)
    {
        dim3 blk(32, 8);
        conv_weight_kernel<<<dim3(QHD/32, CDIM/32),     blk>>>(box_w1,   Wb1, CDIM,   QHD);
        conv_weight_kernel<<<dim3(QHD/32, 2*CDIM/32),   blk>>>(click_w1, Wc1, 2*CDIM, QHD);
        conv_weight_kernel<<<dim3(NOUT/32, QHD/32),     blk>>>(box_w2,   Wb2, QHD,    NOUT);
        conv_weight_kernel<<<dim3(NOUT/32, QHD/32),     blk>>>(click_w2, Wc2, QHD,    NOUT);
    }
    // GEMM1 (both branches): [Xhi|Xlo] @ W1hi + b1, relu -> H (fp16 hi|lo)
    gemm_hmma_kernel<<<dim3(QHD/BN, MROWS/BM, 2), 256, GEMM_SMEM>>>(
        Xb2, Wb1, box_b1, Xc2, Wc1, click_b1,
        K2_BOX1, CDIM, K2_CLK1, 2*CDIM, 0, 0, nullptr, Hb2, Hc2);
    // GEMM2 (both branches): [Hhi|Hlo] @ W2hi + b2 -> out (interleaved layout)
    gemm_hmma_kernel<<<dim3(NOUT/BN, MROWS/BM, 2), 256, GEMM_SMEM>>>(
        Hb2, Wb2, box_b2, Hc2, Wc2, click_b2,
        K2_G2, QHD, K2_G2, QHD, 1, 2, out, nullptr, nullptr);

    mask_fill_kernel<<<(BATCH*(NBQ+NCK)*VQ + 255)/256, 256>>>(box_qmask, click_qmask, out);
}

// round 9
// speedup vs baseline: 4.2043x; 1.6673x over previous
#include <cuda_runtime.h>
#include <cuda_fp16.h>
#include <stdint.h>
#include <math.h>

// ---------------- problem constants ----------------
#define BATCH 32
#define NPROP 256
#define NCLS  19
#define NPTS  4096
#define NBQ   64
#define NCK   64
#define CDIM  256
#define QHD   768
#define VQ    8
#define NOUT  (VQ*QHD)                 // 6144
#define MROWS (BATCH*NBQ)              // 2048
#define FEAT_TOTAL ((size_t)BATCH*(NBQ+NCK)*VQ*QHD)
#define BOX_HALF   (NBQ*VQ*QHD)        // 393216

// pure fp16 K extents
#define K_BOX1  CDIM          // 256
#define K_CLK1  (2*CDIM)      // 512
#define K_G2    QHD           // 768

// ---------------- scratch ----------------
__device__ float g_mnp[BATCH*NPROP*3];
__device__ float g_mxp[BATCH*NPROP*3];
__device__ float g_volp[BATCH*NPROP];
__device__ float g_maskp[BATCH*NPROP];
__device__ float g_mnq[BATCH*NBQ*3];
__device__ float g_mxq[BATCH*NBQ*3];
__device__ float g_volq[BATCH*NBQ];

__device__ __align__(128) __half g_Xbox  [(size_t)MROWS*K_BOX1];
__device__ __align__(128) __half g_Xclick[(size_t)MROWS*K_CLK1];
__device__ __align__(128) __half g_Hbox  [(size_t)MROWS*K_G2];
__device__ __align__(128) __half g_Hclick[(size_t)MROWS*K_G2];
__device__ __align__(128) __half g_Wb1[(size_t)QHD*CDIM];
__device__ __align__(128) __half g_Wc1[(size_t)QHD*2*CDIM];
__device__ __align__(128) __half g_Wb2[(size_t)NOUT*QHD];
__device__ __align__(128) __half g_Wc2[(size_t)NOUT*QHD];

// ---------------- helpers ----------------
static __device__ __forceinline__ uint32_t smem_u32(const void* p) {
    uint32_t a;
    asm("{ .reg .u64 t; cvta.to.shared.u64 t, %1; cvt.u32.u64 %0, t; }" : "=r"(a) : "l"(p));
    return a;
}
#define CPA16(s, g) asm volatile("cp.async.cg.shared.global [%0], [%1], 16;\n" :: "r"(s), "l"(g))
#define CPA_COMMIT() asm volatile("cp.async.commit_group;\n" ::: "memory")

#define LDMX4(r, a) \
    asm volatile("ldmatrix.sync.aligned.m8n8.x4.shared.b16 {%0,%1,%2,%3}, [%4];" \
        : "=r"((r)[0]), "=r"((r)[1]), "=r"((r)[2]), "=r"((r)[3]) : "r"(a))

#define MMA16816(d, a, b0_, b1_) \
    asm volatile("mma.sync.aligned.m16n8k16.row.col.f32.f16.f16.f32 " \
        "{%0,%1,%2,%3}, {%4,%5,%6,%7}, {%8,%9}, {%0,%1,%2,%3};" \
        : "+f"((d)[0]), "+f"((d)[1]), "+f"((d)[2]), "+f"((d)[3]) \
        : "r"((a)[0]), "r"((a)[1]), "r"((a)[2]), "r"((a)[3]), "r"(b0_), "r"(b1_))

// ---------------- prep kernels ----------------
__global__ void prep_props_kernel(const float* __restrict__ logits,
                                  const float* __restrict__ corners) {
    int i = blockIdx.x * blockDim.x + threadIdx.x;
    if (i >= BATCH*NPROP) return;
    const float* lg = logits + (size_t)i*NCLS;
    int am = 0; float best = lg[0];
    #pragma unroll
    for (int c = 1; c < NCLS; c++) { float v = lg[c]; if (v > best) { best = v; am = c; } }
    g_maskp[i] = (am != NCLS-1) ? 1.0f : 0.0f;
    const float* cr = corners + (size_t)i*24;
    float mn[3] = {cr[0], cr[1], cr[2]};
    float mx[3] = {cr[0], cr[1], cr[2]};
    #pragma unroll
    for (int k = 1; k < 8; k++)
        #pragma unroll
        for (int d = 0; d < 3; d++) {
            float v = cr[k*3+d];
            mn[d] = fminf(mn[d], v); mx[d] = fmaxf(mx[d], v);
        }
    float vol = 1.0f;
    #pragma unroll
    for (int d = 0; d < 3; d++) {
        g_mnp[i*3+d] = mn[d]; g_mxp[i*3+d] = mx[d];
        vol *= (mx[d] - mn[d]);
    }
    g_volp[i] = vol;
}

__global__ void prep_queries_kernel(const float* __restrict__ box_query) {
    int i = blockIdx.x * blockDim.x + threadIdx.x;
    if (i >= BATCH*NBQ) return;
    const float* cr = box_query + (size_t)i*24;
    float mn[3] = {cr[0], cr[1], cr[2]};
    float mx[3] = {cr[0], cr[1], cr[2]};
    #pragma unroll
    for (int k = 1; k < 8; k++)
        #pragma unroll
        for (int d = 0; d < 3; d++) {
            float v = cr[k*3+d];
            mn[d] = fminf(mn[d], v); mx[d] = fmaxf(mx[d], v);
        }
    float vol = 1.0f;
    #pragma unroll
    for (int d = 0; d < 3; d++) {
        g_mnq[i*3+d] = mn[d]; g_mxq[i*3+d] = mx[d];
        vol *= (mx[d] - mn[d]);
    }
    g_volq[i] = vol;
}

__global__ __launch_bounds__(256) void box_match_kernel(const float* __restrict__ prop_features) {
    int m = blockIdx.x;
    int b = m >> 6;
    int tid = threadIdx.x;
    float mnq0 = g_mnq[m*3+0], mnq1 = g_mnq[m*3+1], mnq2 = g_mnq[m*3+2];
    float mxq0 = g_mxq[m*3+0], mxq1 = g_mxq[m*3+1], mxq2 = g_mxq[m*3+2];
    float volq = g_volq[m];
    int pi = b*NPROP + tid;
    float i0 = fmaxf(fminf(mxq0, g_mxp[pi*3+0]) - fmaxf(mnq0, g_mnp[pi*3+0]), 0.0f);
    float i1 = fmaxf(fminf(mxq1, g_mxp[pi*3+1]) - fmaxf(mnq1, g_mnp[pi*3+1]), 0.0f);
    float i2 = fmaxf(fminf(mxq2, g_mxp[pi*3+2]) - fmaxf(mnq2, g_mnp[pi*3+2]), 0.0f);
    float inter = i0*i1*i2;
    float iou = inter / (volq + g_volp[pi] - inter + 1e-8f);
    iou *= g_maskp[pi];

    __shared__ float sv[256];
    __shared__ int   si[256];
    sv[tid] = iou; si[tid] = tid;
    __syncthreads();
    #pragma unroll
    for (int off = 128; off > 0; off >>= 1) {
        if (tid < off) {
            float v2 = sv[tid+off]; int j2 = si[tid+off];
            if (v2 > sv[tid] || (v2 == sv[tid] && j2 < si[tid])) { sv[tid] = v2; si[tid] = j2; }
        }
        __syncthreads();
    }
    int idx = si[0];
    float v = prop_features[((size_t)b*NPROP + idx)*CDIM + tid];
    g_Xbox[(size_t)m*K_BOX1 + tid] = __float2half(v);
}

__global__ __launch_bounds__(256) void click_prep_kernel(
    const float* __restrict__ click_query, const float* __restrict__ enc_xyz,
    const float* __restrict__ enc_features, const float* __restrict__ pc_min,
    const float* __restrict__ pc_max, const float* __restrict__ gauss_B) {
    int m = blockIdx.x;
    int b = m >> 6;
    int tid = threadIdx.x;
    float qx = click_query[m*3+0], qy = click_query[m*3+1], qz = click_query[m*3+2];

    const float* xyz = enc_xyz + (size_t)b*NPTS*3;
    float bestd = 3.4e38f; int besti = 0;
    for (int p = tid; p < NPTS; p += 256) {
        float dx = qx - xyz[p*3+0];
        float dy = qy - xyz[p*3+1];
        float dz = qz - xyz[p*3+2];
        float d2 = dx*dx + dy*dy + dz*dz;
        if (d2 < bestd) { bestd = d2; besti = p; }
    }
    __shared__ float sv[256];
    __shared__ int   si[256];
    sv[tid] = bestd; si[tid] = besti;
    __syncthreads();
    #pragma unroll
    for (int off = 128; off > 0; off >>= 1) {
        if (tid < off) {
            float v2 = sv[tid+off]; int j2 = si[tid+off];
            if (v2 < sv[tid] || (v2 == sv[tid] && j2 < si[tid])) { sv[tid] = v2; si[tid] = j2; }
        }
        __syncthreads();
    }
    int nn = si[0];
    size_t rb = (size_t)m*K_CLK1;
    g_Xclick[rb + tid] = __float2half(enc_features[((size_t)b*NPTS + nn)*CDIM + tid]);
    if (tid < 128) {
        float x0 = (qx - pc_min[b*3+0]) / (pc_max[b*3+0] - pc_min[b*3+0]);
        float y0 = (qy - pc_min[b*3+1]) / (pc_max[b*3+1] - pc_min[b*3+1]);
        float z0 = (qz - pc_min[b*3+2]) / (pc_max[b*3+2] - pc_min[b*3+2]);
        const float twopi = 6.283185307179586f;
        float proj = (x0*twopi)*gauss_B[tid] + (y0*twopi)*gauss_B[128+tid] + (z0*twopi)*gauss_B[256+tid];
        g_Xclick[rb + CDIM + tid]       = __float2half(sinf(proj));
        g_Xclick[rb + CDIM + 128 + tid] = __float2half(cosf(proj));
    }
}

// ---------------- weight conversion: W[K,N] fp32 -> Wh[N,K] fp16 ----------------
__global__ __launch_bounds__(256) void conv_weight_kernel(
    const float* __restrict__ W, __half* __restrict__ B2, int K, int N) {
    __shared__ float t[32][33];
    int n0 = blockIdx.x * 32, k0 = blockIdx.y * 32;
    int tx = threadIdx.x, ty = threadIdx.y;   // block (32,8)
    #pragma unroll
    for (int j = 0; j < 4; j++) {
        int k = k0 + ty + j*8;
        t[ty + j*8][tx] = W[(size_t)k*N + n0 + tx];
    }
    __syncthreads();
    #pragma unroll
    for (int j = 0; j < 4; j++) {
        int n = n0 + ty + j*8;
        int k = k0 + tx;
        B2[(size_t)n*K + k] = __float2half(t[tx][ty + j*8]);
    }
}

// ---------------- HMMA fp16 GEMM ----------------
// D[M,N] = A[M,K] x B[N,K]^T; CTA tile 128x128, BK=64, 3-stage cp.async.
// mode 0: relu(d+bias) -> fp16 into outB [M,QHD]
// mode 1: d+bias -> outF + m*6144 + (m>>6)*BOX_HALF
// mode 2: same + BOX_HALF
#define BM 128
#define BN 128
#define STAGE_BYTES 32768      // A 16KB + B 16KB
#define OFF_STAGE 512
#define GEMM_SMEM (OFF_STAGE + 3*STAGE_BYTES)   // 98816

static __device__ __forceinline__ void load_chunk(
    const __half* A2, const __half* B2, int K,
    int bm, int bn, int c, uint32_t sbase, int stage)
{
    int t = threadIdx.x;
    int r = t >> 1;              // 0..127
    int c0 = (t & 1) * 4;        // 0 or 4
    uint32_t stA = sbase + OFF_STAGE + stage*STAGE_BYTES;
    uint32_t stB = stA + 16384;
    const char* ga = (const char*)(A2 + (size_t)(bm + r)*K + c*64);
    const char* gb = (const char*)(B2 + (size_t)(bn + r)*K + c*64);
    uint32_t rowoff = (uint32_t)r * 128;
    int sw = r & 7;
    #pragma unroll
    for (int i = 0; i < 4; i++) {
        int ch = c0 + i;
        uint32_t off = rowoff + (uint32_t)((ch ^ sw) << 4);
        CPA16(stA + off, ga + (ch << 4));
        CPA16(stB + off, gb + (ch << 4));
    }
}

__global__ __launch_bounds__(256, 2) void gemm_hmma_kernel(
    const __half* A0, const __half* B0, const float* bias0,
    const __half* A1, const __half* B1, const float* bias1,
    int k0_, int k1_, int mode0_, int mode1_,
    float* outF, __half* outB0, __half* outB1)
{
    extern __shared__ char smem[];
    const int z = blockIdx.z;
    const __half* A2 = z ? A1 : A0;
    const __half* B2 = z ? B1 : B0;
    const float* bias = z ? bias1 : bias0;
    __half* outB = z ? outB1 : outB0;
    const int K = z ? k1_ : k0_;
    const int mode = z ? mode1_ : mode0_;
    const int bm = blockIdx.y * BM, bn = blockIdx.x * BN;
    const int tid = threadIdx.x, wid = tid >> 5, lane = tid & 31;
    const int warp_m = wid >> 2, warp_n = wid & 3;
    uint32_t sbase = smem_u32(smem);
    float* sBias = (float*)smem;
    if (tid < 128) sBias[tid] = bias[bn + tid];

    float acc[4][4][4];
    #pragma unroll
    for (int mi = 0; mi < 4; mi++)
        #pragma unroll
        for (int nj = 0; nj < 4; nj++)
            #pragma unroll
            for (int e = 0; e < 4; e++) acc[mi][nj][e] = 0.0f;

    const int nch = K >> 6;
    load_chunk(A2, B2, K, bm, bn, 0, sbase, 0); CPA_COMMIT();
    load_chunk(A2, B2, K, bm, bn, 1, sbase, 1); CPA_COMMIT();
    load_chunk(A2, B2, K, bm, bn, 2, sbase, 2); CPA_COMMIT();

    const int lane15 = lane & 15, s7 = lane & 7, hic = lane >> 4;

    for (int c = 0; c < nch; c++) {
        int s = c - (c/3)*3;
        if (c + 3 < nch) { asm volatile("cp.async.wait_group 2;\n" ::: "memory"); }
        else             { asm volatile("cp.async.wait_group 0;\n" ::: "memory"); }
        __syncthreads();

        uint32_t stA = sbase + OFF_STAGE + s*STAGE_BYTES;
        uint32_t stB = stA + 16384;
        uint32_t aBase[4], bBase[2];
        #pragma unroll
        for (int mi = 0; mi < 4; mi++)
            aBase[mi] = stA + (uint32_t)(warp_m*64 + mi*16 + lane15) * 128;
        #pragma unroll
        for (int nt = 0; nt < 2; nt++)
            bBase[nt] = stB + (uint32_t)(warp_n*32 + nt*16 + lane15) * 128;

        #pragma unroll
        for (int ks = 0; ks < 4; ks++) {
            uint32_t coff = (uint32_t)(((2*ks + hic) ^ s7) << 4);
            uint32_t afr[4][4], bfr[2][4];
            #pragma unroll
            for (int mi = 0; mi < 4; mi++) LDMX4(afr[mi], aBase[mi] + coff);
            #pragma unroll
            for (int nt = 0; nt < 2; nt++) LDMX4(bfr[nt], bBase[nt] + coff);
            #pragma unroll
            for (int mi = 0; mi < 4; mi++)
                #pragma unroll
                for (int nj = 0; nj < 4; nj++)
                    MMA16816(acc[mi][nj], afr[mi],
                             bfr[nj>>1][nj&1], bfr[nj>>1][2 + (nj&1)]);
        }
        __syncthreads();
        if (c + 3 < nch) {
            load_chunk(A2, B2, K, bm, bn, c + 3, sbase, s);
            CPA_COMMIT();
        }
    }

    // ---- epilogue ----
    #pragma unroll
    for (int mi = 0; mi < 4; mi++) {
        int rr0 = warp_m*64 + mi*16 + (lane >> 2);
        #pragma unroll
        for (int h = 0; h < 2; h++) {
            int m = bm + rr0 + 8*h;
            size_t rowbase;
            if (mode == 0) rowbase = (size_t)m * K_G2;
            else {
                rowbase = (size_t)m * NOUT + (size_t)(m >> 6) * BOX_HALF;
                if (mode == 2) rowbase += BOX_HALF;
            }
            #pragma unroll
            for (int nj = 0; nj < 4; nj++) {
                int cc = warp_n*32 + nj*8 + 2*(lane & 3);
                float v0 = acc[mi][nj][2*h+0] + sBias[cc];
                float v1 = acc[mi][nj][2*h+1] + sBias[cc+1];
                if (mode == 0) {
                    v0 = fmaxf(v0, 0.0f); v1 = fmaxf(v1, 0.0f);
                    __half2 hp; hp.x = __float2half(v0); hp.y = __float2half(v1);
                    *(__half2*)&outB[rowbase + (size_t)(bn + cc)] = hp;
                } else {
                    float2 v; v.x = v0; v.y = v1;
                    *(float2*)&outF[rowbase + bn + cc] = v;
                }
            }
        }
    }
}

// ---------------- mask tail ----------------
__global__ void mask_fill_kernel(const float* __restrict__ box_qmask,
                                 const float* __restrict__ click_qmask,
                                 float* __restrict__ out) {
    int i = blockIdx.x * blockDim.x + threadIdx.x;
    if (i >= BATCH * (NBQ+NCK) * VQ) return;
    int b = i / ((NBQ+NCK)*VQ);
    int s = i % ((NBQ+NCK)*VQ);
    float v;
    if (s < NBQ*VQ) v = box_qmask[b*NBQ + (s >> 3)];
    else            v = click_qmask[b*NCK + ((s - NBQ*VQ) >> 3)];
    out[FEAT_TOTAL + i] = v;
}

// ---------------- launch ----------------
extern "C" void kernel_launch(void* const* d_in, const int* in_sizes, int n_in,
                              void* d_out, int out_size) {
    const float* sem_cls_logits = (const float*)d_in[0];
    const float* prop_features  = (const float*)d_in[1];
    const float* box_corners    = (const float*)d_in[2];
    const float* enc_xyz        = (const float*)d_in[3];
    const float* enc_features   = (const float*)d_in[4];
    const float* pc_min         = (const float*)d_in[5];
    const float* pc_max         = (const float*)d_in[6];
    const float* box_query      = (const float*)d_in[7];
    const float* box_qmask      = (const float*)d_in[8];
    const float* click_query    = (const float*)d_in[9];
    const float* click_qmask    = (const float*)d_in[10];
    const float* gauss_B        = (const float*)d_in[11];
    const float* box_w1         = (const float*)d_in[12];
    const float* box_b1         = (const float*)d_in[13];
    const float* box_w2         = (const float*)d_in[14];
    const float* box_b2         = (const float*)d_in[15];
    const float* click_w1       = (const float*)d_in[16];
    const float* click_b1       = (const float*)d_in[17];
    const float* click_w2       = (const float*)d_in[18];
    const float* click_b2       = (const float*)d_in[19];
    float* out = (float*)d_out;

    __half *Xb, *Xc, *Hb, *Hc, *Wb1, *Wc1, *Wb2, *Wc2;
    cudaGetSymbolAddress((void**)&Xb,  g_Xbox);
    cudaGetSymbolAddress((void**)&Xc,  g_Xclick);
    cudaGetSymbolAddress((void**)&Hb,  g_Hbox);
    cudaGetSymbolAddress((void**)&Hc,  g_Hclick);
    cudaGetSymbolAddress((void**)&Wb1, g_Wb1);
    cudaGetSymbolAddress((void**)&Wc1, g_Wc1);
    cudaGetSymbolAddress((void**)&Wb2, g_Wb2);
    cudaGetSymbolAddress((void**)&Wc2, g_Wc2);

    cudaFuncSetAttribute(gemm_hmma_kernel,
                         cudaFuncAttributeMaxDynamicSharedMemorySize, GEMM_SMEM);

    // prep
    prep_props_kernel<<<(BATCH*NPROP + 255)/256, 256>>>(sem_cls_logits, box_corners);
    prep_queries_kernel<<<(BATCH*NBQ + 255)/256, 256>>>(box_query);
    box_match_kernel<<<MROWS, 256>>>(prop_features);
    click_prep_kernel<<<MROWS, 256>>>(click_query, enc_xyz, enc_features,
                                      pc_min, pc_max, gauss_B);
    // weight conversion (W[K,N] fp32 -> Wh[N,K] fp16)
    {
        dim3 blk(32, 8);
        conv_weight_kernel<<<dim3(QHD/32, CDIM/32),     blk>>>(box_w1,   Wb1, CDIM,   QHD);
        conv_weight_kernel<<<dim3(QHD/32, 2*CDIM/32),   blk>>>(click_w1, Wc1, 2*CDIM, QHD);
        conv_weight_kernel<<<dim3(NOUT/32, QHD/32),     blk>>>(box_w2,   Wb2, QHD,    NOUT);
        conv_weight_kernel<<<dim3(NOUT/32, QHD/32),     blk>>>(click_w2, Wc2, QHD,    NOUT);
    }
    // GEMM1 (both branches): X @ W1 + b1, relu -> H (fp16)
    gemm_hmma_kernel<<<dim3(QHD/BN, MROWS/BM, 2), 256, GEMM_SMEM>>>(
        Xb, Wb1, box_b1, Xc, Wc1, click_b1,
        K_BOX1, K_CLK1, 0, 0, nullptr, Hb, Hc);
    // GEMM2 (both branches): H @ W2 + b2 -> out (interleaved layout)
    gemm_hmma_kernel<<<dim3(NOUT/BN, MROWS/BM, 2), 256, GEMM_SMEM>>>(
        Hb, Wb2, box_b2, Hc, Wc2, click_b2,
        K_G2, K_G2, 1, 2, out, nullptr, nullptr);

    mask_fill_kernel<<<(BATCH*(NBQ+NCK)*VQ + 255)/256, 256>>>(box_qmask, click_qmask, out);
}

// round 10
// speedup vs baseline: 4.7577x; 1.1316x over previous
#include <cuda_runtime.h>
#include <cuda_fp16.h>
#include <stdint.h>
#include <math.h>

// ---------------- problem constants ----------------
#define BATCH 32
#define NPROP 256
#define NCLS  19
#define NPTS  4096
#define NBQ   64
#define NCK   64
#define CDIM  256
#define QHD   768
#define VQ    8
#define NOUT  (VQ*QHD)                 // 6144
#define MROWS (BATCH*NBQ)              // 2048
#define FEAT_TOTAL ((size_t)BATCH*(NBQ+NCK)*VQ*QHD)
#define BOX_HALF   (NBQ*VQ*QHD)        // 393216

// pure fp16 K extents
#define K_BOX1  CDIM          // 256
#define K_CLK1  (2*CDIM)      // 512
#define K_G2    QHD           // 768

// ---------------- scratch ----------------
__device__ float g_mnp[BATCH*NPROP*3];
__device__ float g_mxp[BATCH*NPROP*3];
__device__ float g_volp[BATCH*NPROP];
__device__ float g_maskp[BATCH*NPROP];
__device__ float g_mnq[BATCH*NBQ*3];
__device__ float g_mxq[BATCH*NBQ*3];
__device__ float g_volq[BATCH*NBQ];

__device__ __align__(128) __half g_Xbox  [(size_t)MROWS*K_BOX1];
__device__ __align__(128) __half g_Xclick[(size_t)MROWS*K_CLK1];
__device__ __align__(128) __half g_Hbox  [(size_t)MROWS*K_G2];
__device__ __align__(128) __half g_Hclick[(size_t)MROWS*K_G2];
__device__ __align__(128) __half g_Wb1[(size_t)QHD*CDIM];
__device__ __align__(128) __half g_Wc1[(size_t)QHD*2*CDIM];
__device__ __align__(128) __half g_Wb2[(size_t)NOUT*QHD];
__device__ __align__(128) __half g_Wc2[(size_t)NOUT*QHD];

// ---------------- helpers ----------------
static __device__ __forceinline__ uint32_t smem_u32(const void* p) {
    uint32_t a;
    asm("{ .reg .u64 t; cvta.to.shared.u64 t, %1; cvt.u32.u64 %0, t; }" : "=r"(a) : "l"(p));
    return a;
}
#define CPA16(s, g) asm volatile("cp.async.cg.shared.global [%0], [%1], 16;\n" :: "r"(s), "l"(g))
#define CPA_COMMIT() asm volatile("cp.async.commit_group;\n" ::: "memory")

#define LDMX4(r, a) \
    asm volatile("ldmatrix.sync.aligned.m8n8.x4.shared.b16 {%0,%1,%2,%3}, [%4];" \
        : "=r"((r)[0]), "=r"((r)[1]), "=r"((r)[2]), "=r"((r)[3]) : "r"(a))

#define MMA16816(d, a, b0_, b1_) \
    asm volatile("mma.sync.aligned.m16n8k16.row.col.f32.f16.f16.f32 " \
        "{%0,%1,%2,%3}, {%4,%5,%6,%7}, {%8,%9}, {%0,%1,%2,%3};" \
        : "+f"((d)[0]), "+f"((d)[1]), "+f"((d)[2]), "+f"((d)[3]) \
        : "r"((a)[0]), "r"((a)[1]), "r"((a)[2]), "r"((a)[3]), "r"(b0_), "r"(b1_))

// ---------------- prep kernels ----------------
__global__ void prep_props_kernel(const float* __restrict__ logits,
                                  const float* __restrict__ corners) {
    int i = blockIdx.x * blockDim.x + threadIdx.x;
    if (i >= BATCH*NPROP) return;
    const float* lg = logits + (size_t)i*NCLS;
    int am = 0; float best = lg[0];
    #pragma unroll
    for (int c = 1; c < NCLS; c++) { float v = lg[c]; if (v > best) { best = v; am = c; } }
    g_maskp[i] = (am != NCLS-1) ? 1.0f : 0.0f;
    const float* cr = corners + (size_t)i*24;
    float mn[3] = {cr[0], cr[1], cr[2]};
    float mx[3] = {cr[0], cr[1], cr[2]};
    #pragma unroll
    for (int k = 1; k < 8; k++)
        #pragma unroll
        for (int d = 0; d < 3; d++) {
            float v = cr[k*3+d];
            mn[d] = fminf(mn[d], v); mx[d] = fmaxf(mx[d], v);
        }
    float vol = 1.0f;
    #pragma unroll
    for (int d = 0; d < 3; d++) {
        g_mnp[i*3+d] = mn[d]; g_mxp[i*3+d] = mx[d];
        vol *= (mx[d] - mn[d]);
    }
    g_volp[i] = vol;
}

__global__ void prep_queries_kernel(const float* __restrict__ box_query) {
    int i = blockIdx.x * blockDim.x + threadIdx.x;
    if (i >= BATCH*NBQ) return;
    const float* cr = box_query + (size_t)i*24;
    float mn[3] = {cr[0], cr[1], cr[2]};
    float mx[3] = {cr[0], cr[1], cr[2]};
    #pragma unroll
    for (int k = 1; k < 8; k++)
        #pragma unroll
        for (int d = 0; d < 3; d++) {
            float v = cr[k*3+d];
            mn[d] = fminf(mn[d], v); mx[d] = fmaxf(mx[d], v);
        }
    float vol = 1.0f;
    #pragma unroll
    for (int d = 0; d < 3; d++) {
        g_mnq[i*3+d] = mn[d]; g_mxq[i*3+d] = mx[d];
        vol *= (mx[d] - mn[d]);
    }
    g_volq[i] = vol;
}

__global__ __launch_bounds__(256) void box_match_kernel(const float* __restrict__ prop_features) {
    int m = blockIdx.x;
    int b = m >> 6;
    int tid = threadIdx.x;
    float mnq0 = g_mnq[m*3+0], mnq1 = g_mnq[m*3+1], mnq2 = g_mnq[m*3+2];
    float mxq0 = g_mxq[m*3+0], mxq1 = g_mxq[m*3+1], mxq2 = g_mxq[m*3+2];
    float volq = g_volq[m];
    int pi = b*NPROP + tid;
    float i0 = fmaxf(fminf(mxq0, g_mxp[pi*3+0]) - fmaxf(mnq0, g_mnp[pi*3+0]), 0.0f);
    float i1 = fmaxf(fminf(mxq1, g_mxp[pi*3+1]) - fmaxf(mnq1, g_mnp[pi*3+1]), 0.0f);
    float i2 = fmaxf(fminf(mxq2, g_mxp[pi*3+2]) - fmaxf(mnq2, g_mnp[pi*3+2]), 0.0f);
    float inter = i0*i1*i2;
    float iou = inter / (volq + g_volp[pi] - inter + 1e-8f);
    iou *= g_maskp[pi];

    __shared__ float sv[256];
    __shared__ int   si[256];
    sv[tid] = iou; si[tid] = tid;
    __syncthreads();
    #pragma unroll
    for (int off = 128; off > 0; off >>= 1) {
        if (tid < off) {
            float v2 = sv[tid+off]; int j2 = si[tid+off];
            if (v2 > sv[tid] || (v2 == sv[tid] && j2 < si[tid])) { sv[tid] = v2; si[tid] = j2; }
        }
        __syncthreads();
    }
    int idx = si[0];
    float v = prop_features[((size_t)b*NPROP + idx)*CDIM + tid];
    g_Xbox[(size_t)m*K_BOX1 + tid] = __float2half(v);
}

__global__ __launch_bounds__(256) void click_prep_kernel(
    const float* __restrict__ click_query, const float* __restrict__ enc_xyz,
    const float* __restrict__ enc_features, const float* __restrict__ pc_min,
    const float* __restrict__ pc_max, const float* __restrict__ gauss_B) {
    int m = blockIdx.x;
    int b = m >> 6;
    int tid = threadIdx.x;
    float qx = click_query[m*3+0], qy = click_query[m*3+1], qz = click_query[m*3+2];

    const float* xyz = enc_xyz + (size_t)b*NPTS*3;
    float bestd = 3.4e38f; int besti = 0;
    for (int p = tid; p < NPTS; p += 256) {
        float dx = qx - xyz[p*3+0];
        float dy = qy - xyz[p*3+1];
        float dz = qz - xyz[p*3+2];
        float d2 = dx*dx + dy*dy + dz*dz;
        if (d2 < bestd) { bestd = d2; besti = p; }
    }
    __shared__ float sv[256];
    __shared__ int   si[256];
    sv[tid] = bestd; si[tid] = besti;
    __syncthreads();
    #pragma unroll
    for (int off = 128; off > 0; off >>= 1) {
        if (tid < off) {
            float v2 = sv[tid+off]; int j2 = si[tid+off];
            if (v2 < sv[tid] || (v2 == sv[tid] && j2 < si[tid])) { sv[tid] = v2; si[tid] = j2; }
        }
        __syncthreads();
    }
    int nn = si[0];
    size_t rb = (size_t)m*K_CLK1;
    g_Xclick[rb + tid] = __float2half(enc_features[((size_t)b*NPTS + nn)*CDIM + tid]);
    if (tid < 128) {
        float x0 = (qx - pc_min[b*3+0]) / (pc_max[b*3+0] - pc_min[b*3+0]);
        float y0 = (qy - pc_min[b*3+1]) / (pc_max[b*3+1] - pc_min[b*3+1]);
        float z0 = (qz - pc_min[b*3+2]) / (pc_max[b*3+2] - pc_min[b*3+2]);
        const float twopi = 6.283185307179586f;
        float proj = (x0*twopi)*gauss_B[tid] + (y0*twopi)*gauss_B[128+tid] + (z0*twopi)*gauss_B[256+tid];
        g_Xclick[rb + CDIM + tid]       = __float2half(sinf(proj));
        g_Xclick[rb + CDIM + 128 + tid] = __float2half(cosf(proj));
    }
}

// ---------------- weight conversion: W[K,N] fp32 -> Wh[N,K] fp16 ----------------
__global__ __launch_bounds__(256) void conv_weight_kernel(
    const float* __restrict__ W, __half* __restrict__ B2, int K, int N) {
    __shared__ float t[32][33];
    int n0 = blockIdx.x * 32, k0 = blockIdx.y * 32;
    int tx = threadIdx.x, ty = threadIdx.y;   // block (32,8)
    #pragma unroll
    for (int j = 0; j < 4; j++) {
        int k = k0 + ty + j*8;
        t[ty + j*8][tx] = W[(size_t)k*N + n0 + tx];
    }
    __syncthreads();
    #pragma unroll
    for (int j = 0; j < 4; j++) {
        int n = n0 + ty + j*8;
        int k = k0 + tx;
        B2[(size_t)n*K + k] = __float2half(t[tx][ty + j*8]);
    }
}

// ---------------- HMMA fp16 GEMM ----------------
// D[M,N] = A[M,K] x B[N,K]^T; CTA tile 128x256, warp tile 64x64 (2x4 warps),
// BK=64, 3-stage cp.async pipeline, 1 CTA/SM.
// mode 0: relu(d+bias) -> fp16 into outB [M,QHD]
// mode 1: d+bias -> outF + m*6144 + (m>>6)*BOX_HALF
// mode 2: same + BOX_HALF
#define BM 128
#define BN 256
#define A_STAGE 16384          // 128 x 64 fp16
#define B_STAGE 32768          // 256 x 64 fp16
#define STAGE_BYTES (A_STAGE + B_STAGE)   // 49152
#define OFF_STAGE 1024
#define GEMM_SMEM (OFF_STAGE + 3*STAGE_BYTES)   // 148480

static __device__ __forceinline__ void load_chunk(
    const __half* A2, const __half* B2, int K,
    int bm, int bn, int c, uint32_t sbase, int stage)
{
    int t = threadIdx.x;
    uint32_t stA = sbase + OFF_STAGE + stage*STAGE_BYTES;
    uint32_t stB = stA + A_STAGE;
    // A: 128 rows x 128B = 1024 16B-units; 4 per thread
    #pragma unroll
    for (int i = 0; i < 4; i++) {
        int u = t + 256*i;
        int r = u >> 3, c16 = u & 7;
        uint32_t off = (uint32_t)r*128 + (uint32_t)((c16 ^ (r & 7)) << 4);
        CPA16(stA + off, (const char*)(A2 + (size_t)(bm + r)*K + c*64) + (c16 << 4));
    }
    // B: 256 rows x 128B = 2048 16B-units; 8 per thread
    #pragma unroll
    for (int i = 0; i < 8; i++) {
        int u = t + 256*i;
        int r = u >> 3, c16 = u & 7;
        uint32_t off = (uint32_t)r*128 + (uint32_t)((c16 ^ (r & 7)) << 4);
        CPA16(stB + off, (const char*)(B2 + (size_t)(bn + r)*K + c*64) + (c16 << 4));
    }
}

__global__ __launch_bounds__(256, 1) void gemm_hmma_kernel(
    const __half* A0, const __half* B0, const float* bias0,
    const __half* A1, const __half* B1, const float* bias1,
    int k0_, int k1_, int mode0_, int mode1_,
    float* outF, __half* outB0, __half* outB1)
{
    extern __shared__ char smem[];
    const int z = blockIdx.z;
    const __half* A2 = z ? A1 : A0;
    const __half* B2 = z ? B1 : B0;
    const float* bias = z ? bias1 : bias0;
    __half* outB = z ? outB1 : outB0;
    const int K = z ? k1_ : k0_;
    const int mode = z ? mode1_ : mode0_;
    const int bm = blockIdx.y * BM, bn = blockIdx.x * BN;
    const int tid = threadIdx.x, wid = tid >> 5, lane = tid & 31;
    const int warp_m = wid >> 2, warp_n = wid & 3;   // 2 x 4 warps, 64x64 each
    uint32_t sbase = smem_u32(smem);
    float* sBias = (float*)smem;
    sBias[tid] = bias[bn + tid];

    float acc[4][8][4];
    #pragma unroll
    for (int mi = 0; mi < 4; mi++)
        #pragma unroll
        for (int nj = 0; nj < 8; nj++)
            #pragma unroll
            for (int e = 0; e < 4; e++) acc[mi][nj][e] = 0.0f;

    const int nch = K >> 6;
    load_chunk(A2, B2, K, bm, bn, 0, sbase, 0); CPA_COMMIT();
    load_chunk(A2, B2, K, bm, bn, 1, sbase, 1); CPA_COMMIT();
    load_chunk(A2, B2, K, bm, bn, 2, sbase, 2); CPA_COMMIT();

    const int lane15 = lane & 15, s7 = lane & 7, hic = lane >> 4;

    for (int c = 0; c < nch; c++) {
        int s = c - (c/3)*3;
        if (c + 3 < nch) { asm volatile("cp.async.wait_group 2;\n" ::: "memory"); }
        else             { asm volatile("cp.async.wait_group 0;\n" ::: "memory"); }
        __syncthreads();

        uint32_t stA = sbase + OFF_STAGE + s*STAGE_BYTES;
        uint32_t stB = stA + A_STAGE;
        uint32_t aBase[4], bBase[4];
        #pragma unroll
        for (int mi = 0; mi < 4; mi++)
            aBase[mi] = stA + (uint32_t)(warp_m*64 + mi*16 + lane15) * 128;
        #pragma unroll
        for (int nt = 0; nt < 4; nt++)
            bBase[nt] = stB + (uint32_t)(warp_n*64 + nt*16 + lane15) * 128;

        #pragma unroll
        for (int ks = 0; ks < 4; ks++) {
            uint32_t coff = (uint32_t)(((2*ks + hic) ^ s7) << 4);
            uint32_t afr[4][4], bfr[4][4];
            #pragma unroll
            for (int mi = 0; mi < 4; mi++) LDMX4(afr[mi], aBase[mi] + coff);
            #pragma unroll
            for (int nt = 0; nt < 4; nt++) LDMX4(bfr[nt], bBase[nt] + coff);
            #pragma unroll
            for (int mi = 0; mi < 4; mi++)
                #pragma unroll
                for (int nj = 0; nj < 8; nj++)
                    MMA16816(acc[mi][nj], afr[mi],
                             bfr[nj>>1][nj&1], bfr[nj>>1][2 + (nj&1)]);
        }
        __syncthreads();
        if (c + 3 < nch) {
            load_chunk(A2, B2, K, bm, bn, c + 3, sbase, s);
            CPA_COMMIT();
        }
    }

    // ---- epilogue ----
    #pragma unroll
    for (int mi = 0; mi < 4; mi++) {
        int rr0 = warp_m*64 + mi*16 + (lane >> 2);
        #pragma unroll
        for (int h = 0; h < 2; h++) {
            int m = bm + rr0 + 8*h;
            size_t rowbase;
            if (mode == 0) rowbase = (size_t)m * K_G2;
            else {
                rowbase = (size_t)m * NOUT + (size_t)(m >> 6) * BOX_HALF;
                if (mode == 2) rowbase += BOX_HALF;
            }
            #pragma unroll
            for (int nj = 0; nj < 8; nj++) {
                int cc = warp_n*64 + nj*8 + 2*(lane & 3);
                float v0 = acc[mi][nj][2*h+0] + sBias[cc];
                float v1 = acc[mi][nj][2*h+1] + sBias[cc+1];
                if (mode == 0) {
                    v0 = fmaxf(v0, 0.0f); v1 = fmaxf(v1, 0.0f);
                    __half2 hp; hp.x = __float2half(v0); hp.y = __float2half(v1);
                    *(__half2*)&outB[rowbase + (size_t)(bn + cc)] = hp;
                } else {
                    float2 v; v.x = v0; v.y = v1;
                    *(float2*)&outF[rowbase + bn + cc] = v;
                }
            }
        }
    }
}

// ---------------- mask tail ----------------
__global__ void mask_fill_kernel(const float* __restrict__ box_qmask,
                                 const float* __restrict__ click_qmask,
                                 float* __restrict__ out) {
    int i = blockIdx.x * blockDim.x + threadIdx.x;
    if (i >= BATCH * (NBQ+NCK) * VQ) return;
    int b = i / ((NBQ+NCK)*VQ);
    int s = i % ((NBQ+NCK)*VQ);
    float v;
    if (s < NBQ*VQ) v = box_qmask[b*NBQ + (s >> 3)];
    else            v = click_qmask[b*NCK + ((s - NBQ*VQ) >> 3)];
    out[FEAT_TOTAL + i] = v;
}

// ---------------- launch ----------------
extern "C" void kernel_launch(void* const* d_in, const int* in_sizes, int n_in,
                              void* d_out, int out_size) {
    const float* sem_cls_logits = (const float*)d_in[0];
    const float* prop_features  = (const float*)d_in[1];
    const float* box_corners    = (const float*)d_in[2];
    const float* enc_xyz        = (const float*)d_in[3];
    const float* enc_features   = (const float*)d_in[4];
    const float* pc_min         = (const float*)d_in[5];
    const float* pc_max         = (const float*)d_in[6];
    const float* box_query      = (const float*)d_in[7];
    const float* box_qmask      = (const float*)d_in[8];
    const float* click_query    = (const float*)d_in[9];
    const float* click_qmask    = (const float*)d_in[10];
    const float* gauss_B        = (const float*)d_in[11];
    const float* box_w1         = (const float*)d_in[12];
    const float* box_b1         = (const float*)d_in[13];
    const float* box_w2         = (const float*)d_in[14];
    const float* box_b2         = (const float*)d_in[15];
    const float* click_w1       = (const float*)d_in[16];
    const float* click_b1       = (const float*)d_in[17];
    const float* click_w2       = (const float*)d_in[18];
    const float* click_b2       = (const float*)d_in[19];
    float* out = (float*)d_out;

    __half *Xb, *Xc, *Hb, *Hc, *Wb1, *Wc1, *Wb2, *Wc2;
    cudaGetSymbolAddress((void**)&Xb,  g_Xbox);
    cudaGetSymbolAddress((void**)&Xc,  g_Xclick);
    cudaGetSymbolAddress((void**)&Hb,  g_Hbox);
    cudaGetSymbolAddress((void**)&Hc,  g_Hclick);
    cudaGetSymbolAddress((void**)&Wb1, g_Wb1);
    cudaGetSymbolAddress((void**)&Wc1, g_Wc1);
    cudaGetSymbolAddress((void**)&Wb2, g_Wb2);
    cudaGetSymbolAddress((void**)&Wc2, g_Wc2);

    cudaFuncSetAttribute(gemm_hmma_kernel,
                         cudaFuncAttributeMaxDynamicSharedMemorySize, GEMM_SMEM);

    // prep
    prep_props_kernel<<<(BATCH*NPROP + 255)/256, 256>>>(sem_cls_logits, box_corners);
    prep_queries_kernel<<<(BATCH*NBQ + 255)/256, 256>>>(box_query);
    box_match_kernel<<<MROWS, 256>>>(prop_features);
    click_prep_kernel<<<MROWS, 256>>>(click_query, enc_xyz, enc_features,
                                      pc_min, pc_max, gauss_B);
    // weight conversion (W[K,N] fp32 -> Wh[N,K] fp16)
    {
        dim3 blk(32, 8);
        conv_weight_kernel<<<dim3(QHD/32, CDIM/32),     blk>>>(box_w1,   Wb1, CDIM,   QHD);
        conv_weight_kernel<<<dim3(QHD/32, 2*CDIM/32),   blk>>>(click_w1, Wc1, 2*CDIM, QHD);
        conv_weight_kernel<<<dim3(NOUT/32, QHD/32),     blk>>>(box_w2,   Wb2, QHD,    NOUT);
        conv_weight_kernel<<<dim3(NOUT/32, QHD/32),     blk>>>(click_w2, Wc2, QHD,    NOUT);
    }
    // GEMM1 (both branches): X @ W1 + b1, relu -> H (fp16)
    gemm_hmma_kernel<<<dim3(QHD/BN, MROWS/BM, 2), 256, GEMM_SMEM>>>(
        Xb, Wb1, box_b1, Xc, Wc1, click_b1,
        K_BOX1, K_CLK1, 0, 0, nullptr, Hb, Hc);
    // GEMM2 (both branches): H @ W2 + b2 -> out (interleaved layout)
    gemm_hmma_kernel<<<dim3(NOUT/BN, MROWS/BM, 2), 256, GEMM_SMEM>>>(
        Hb, Wb2, box_b2, Hc, Wc2, click_b2,
        K_G2, K_G2, 1, 2, out, nullptr, nullptr);

    mask_fill_kernel<<<(BATCH*(NBQ+NCK)*VQ + 255)/256, 256>>>(box_qmask, click_qmask, out);
}